// round 6
// baseline (speedup 1.0000x reference)
#include <cuda_runtime.h>
#include <cuda_bf16.h>
#include <cstdint>
#include <math.h>

// Problem dims
#define BB   2
#define SS   2048
#define HID  512
#define NHH  8
#define DD   64

// ---------------- scratch (static device globals; no allocation) ----------------
__device__ float g_qh[(size_t)BB * SS * HID];
__device__ float g_kh[(size_t)BB * SS * HID];
__device__ float g_vh[(size_t)BB * SS * HID];
__device__ __nv_bfloat16 g_Xh[(size_t)BB * NHH * SS * SS];   // hi(bf16) of masked scores
__device__ __nv_bfloat16 g_Xl[(size_t)BB * NHH * SS * SS];   // lo residual
__device__ __nv_bfloat16 g_whT[(size_t)BB * SS * SS];        // w^T hi  [b][l][k]
__device__ __nv_bfloat16 g_wlT[(size_t)BB * SS * SS];        // w^T lo
__device__ float g_Y [(size_t)BB * NHH * SS * SS];           // X@w, softmax in-place
__device__ float g_O [(size_t)BB * SS * HID];

// ================= helpers =================
__device__ __forceinline__ uint32_t smem_u32(const void* p) {
    uint32_t a;
    asm("{ .reg .u64 t; cvta.to.shared.u64 t, %1; cvt.u32.u64 %0, t; }" : "=r"(a) : "l"(p));
    return a;
}
__device__ __forceinline__ uint32_t sw128(uint32_t o) { return o ^ ((o >> 3) & 0x70); }

__device__ __forceinline__ void ldsm4(uint32_t& r0, uint32_t& r1, uint32_t& r2, uint32_t& r3, uint32_t addr) {
    asm volatile("ldmatrix.sync.aligned.m8n8.x4.shared.b16 {%0,%1,%2,%3}, [%4];"
        : "=r"(r0), "=r"(r1), "=r"(r2), "=r"(r3) : "r"(addr));
}
__device__ __forceinline__ void mma16816(float* d, const uint32_t* a, const uint32_t* b) {
    asm volatile("mma.sync.aligned.m16n8k16.row.col.f32.bf16.bf16.f32 "
        "{%0,%1,%2,%3}, {%4,%5,%6,%7}, {%8,%9}, {%0,%1,%2,%3};"
        : "+f"(d[0]), "+f"(d[1]), "+f"(d[2]), "+f"(d[3])
        : "r"(a[0]), "r"(a[1]), "r"(a[2]), "r"(a[3]), "r"(b[0]), "r"(b[1]));
}
__device__ __forceinline__ void cpa16(uint32_t dst, const void* src) {
    asm volatile("cp.async.cg.shared.global [%0], [%1], 16;" :: "r"(dst), "l"(src));
}

// ================= x@w GEMM via mma.sync bf16 (3-term split) =================
// Y[m,n] = sum_k Xh*wh + Xh*wl + Xl*wh, fp32 accum.
// CTA 256(M) x 128(N), 8 warps (4m x 2n), warp tile 64x64, K-chunk 64.
// Stage: Ah(32K) Al(32K) Bh(16K) Bl(16K) = 96KB; 2 stages = 192KB.
#define XW_STAGE 98304
#define XW_SMEM  (2 * XW_STAGE)
#define XW_NCHUNK 32

__device__ __forceinline__ void xw_load(
    uint32_t sbase, int slot, int chunk,
    const __nv_bfloat16* __restrict__ Xh, const __nv_bfloat16* __restrict__ Xl,
    const __nv_bfloat16* __restrict__ whb, const __nv_bfloat16* __restrict__ wlb,
    int m0, int n0, int tid)
{
    const int kk = chunk * 64;
    const uint32_t base = sbase + (uint32_t)slot * XW_STAGE;
    // A: 256 rows x 128B, hi+lo. thread t handles full row t of both.
    {
        const __nv_bfloat16* a1 = Xh + (size_t)(m0 + tid) * SS + kk;
        const __nv_bfloat16* a2 = Xl + (size_t)(m0 + tid) * SS + kk;
        const uint32_t roff = (uint32_t)tid * 128;
#pragma unroll
        for (int c = 0; c < 8; c++) {
            uint32_t s = sw128(roff + c * 16);
            cpa16(base +         s, a1 + c * 8);
            cpa16(base + 32768 + s, a2 + c * 8);
        }
    }
    // B: 128 rows x 128B, hi+lo. threads 0-127 -> Bh, 128-255 -> Bl.
    {
        const int row = tid & 127;
        const __nv_bfloat16* b = ((tid >> 7) ? wlb : whb) + (size_t)(n0 + row) * SS + kk;
        const uint32_t bb = base + 65536 + (uint32_t)(tid >> 7) * 16384;
        const uint32_t roff = (uint32_t)row * 128;
#pragma unroll
        for (int c = 0; c < 8; c++) {
            uint32_t s = sw128(roff + c * 16);
            cpa16(bb + s, b + c * 8);
        }
    }
}

__device__ __forceinline__ void xw_compute(uint32_t stg, int wm, int wn, int lane,
                                           float acc[4][8][4])
{
    const uint32_t aH = stg, aL = stg + 32768, bH = stg + 65536, bL = stg + 81920;
    const uint32_t a_base = (uint32_t)(wm * 64 + (lane & 15)) * 128 + (uint32_t)((lane >> 4) * 16);
    const uint32_t b_base = (uint32_t)(wn * 64 + (lane & 7) + ((lane >> 4) << 3)) * 128
                          + (uint32_t)(((lane >> 3) & 1) * 16);
#pragma unroll
    for (int ks = 0; ks < 4; ks++) {
        const uint32_t k0b = (uint32_t)ks * 32;
        uint32_t ah[4][4], al[4][4], bh[8][2], bl[8][2];
#pragma unroll
        for (int mb = 0; mb < 4; mb++) {
            uint32_t s = sw128(a_base + (uint32_t)mb * 2048 + k0b);
            ldsm4(ah[mb][0], ah[mb][1], ah[mb][2], ah[mb][3], aH + s);
            ldsm4(al[mb][0], al[mb][1], al[mb][2], al[mb][3], aL + s);
        }
#pragma unroll
        for (int nb2 = 0; nb2 < 4; nb2++) {
            uint32_t s = sw128(b_base + (uint32_t)nb2 * 2048 + k0b);
            uint32_t r0, r1, r2, r3;
            ldsm4(r0, r1, r2, r3, bH + s);
            bh[2 * nb2][0] = r0; bh[2 * nb2][1] = r1;
            bh[2 * nb2 + 1][0] = r2; bh[2 * nb2 + 1][1] = r3;
            ldsm4(r0, r1, r2, r3, bL + s);
            bl[2 * nb2][0] = r0; bl[2 * nb2][1] = r1;
            bl[2 * nb2 + 1][0] = r2; bl[2 * nb2 + 1][1] = r3;
        }
#pragma unroll
        for (int mb = 0; mb < 4; mb++)
#pragma unroll
            for (int nb = 0; nb < 8; nb++) {
                mma16816(acc[mb][nb], ah[mb], bh[nb]);
                mma16816(acc[mb][nb], ah[mb], bl[nb]);
                mma16816(acc[mb][nb], al[mb], bh[nb]);
            }
    }
}

__global__ __launch_bounds__(256, 1)
void xw_mma_kernel(const __nv_bfloat16* __restrict__ Xh, const __nv_bfloat16* __restrict__ Xl,
                   const __nv_bfloat16* __restrict__ whT, const __nv_bfloat16* __restrict__ wlT,
                   float* __restrict__ Y)
{
    extern __shared__ char smem[];
    const uint32_t sbase = smem_u32(smem);
    const int tid  = threadIdx.x;
    const int wid  = tid >> 5;
    const int lane = tid & 31;
    const int wm   = wid & 3;
    const int wn   = wid >> 2;
    const int n0   = blockIdx.x * 128;
    const int m0   = blockIdx.y * 256;
    const int batch = m0 >> 14;                 // 16384 rows per batch
    const __nv_bfloat16* whb = whT + (size_t)batch * SS * SS;
    const __nv_bfloat16* wlb = wlT + (size_t)batch * SS * SS;

    float acc[4][8][4];
#pragma unroll
    for (int i = 0; i < 4; i++)
#pragma unroll
        for (int j = 0; j < 8; j++)
#pragma unroll
            for (int r = 0; r < 4; r++) acc[i][j][r] = 0.0f;

    // prologue: 2 stages
#pragma unroll
    for (int j = 0; j < 2; j++) {
        xw_load(sbase, j, j, Xh, Xl, whb, wlb, m0, n0, tid);
        asm volatile("cp.async.commit_group;" ::: "memory");
    }

    for (int i = 0; i < XW_NCHUNK; i++) {
        const int s = i & 1;
        asm volatile("cp.async.wait_group 1;" ::: "memory");
        __syncthreads();
        xw_compute(sbase + (uint32_t)s * XW_STAGE, wm, wn, lane, acc);
        __syncthreads();
        if (i + 2 < XW_NCHUNK)
            xw_load(sbase, s, i + 2, Xh, Xl, whb, wlb, m0, n0, tid);
        asm volatile("cp.async.commit_group;" ::: "memory");
    }

    // epilogue: store fp32 accumulators
    const int r  = lane >> 2;
    const int c2 = (lane & 3) * 2;
#pragma unroll
    for (int mb = 0; mb < 4; mb++) {
        const int row = m0 + wm * 64 + mb * 16 + r;
#pragma unroll
        for (int nb = 0; nb < 8; nb++) {
            const int col = n0 + wn * 64 + nb * 8 + c2;
            float2 v0 = make_float2(acc[mb][nb][0], acc[mb][nb][1]);
            float2 v1 = make_float2(acc[mb][nb][2], acc[mb][nb][3]);
            *(float2*)(Y + (size_t)row * SS + col)       = v0;
            *(float2*)(Y + (size_t)(row + 8) * SS + col) = v1;
        }
    }
}

// ================= w -> bf16 hi/lo transpose =================
__global__ __launch_bounds__(256)
void convw_kernel(const float* __restrict__ w, __nv_bfloat16* __restrict__ whT, __nv_bfloat16* __restrict__ wlT)
{
    __shared__ float t[32][33];
    const int b  = blockIdx.z;
    const int k0 = blockIdx.y * 32;
    const int l0 = blockIdx.x * 32;
    const float* wb = w + (size_t)b * SS * SS;
    const int tx = threadIdx.x & 31;
    const int ty = threadIdx.x >> 5;     // 0..7
#pragma unroll
    for (int i = 0; i < 4; i++)
        t[ty + 8 * i][tx] = wb[(size_t)(k0 + ty + 8 * i) * SS + l0 + tx];
    __syncthreads();
#pragma unroll
    for (int i = 0; i < 4; i++) {
        float v = t[tx][ty + 8 * i];                     // w[b][k0+tx][l0+ty+8i]
        size_t idx = (size_t)b * SS * SS + (size_t)(l0 + ty + 8 * i) * SS + (k0 + tx);
        __nv_bfloat16 h = __float2bfloat16(v);
        whT[idx] = h;
        wlT[idx] = __float2bfloat16(v - __bfloat162float(h));
    }
}

// ---------------- generic batched fp32 GEMM (projections, PV, out-proj) ----------------
template <bool BT, bool BIAS>
__global__ __launch_bounds__(256)
void gemm128(const float* __restrict__ A, const float* __restrict__ Bm,
             const float* __restrict__ bias, float* __restrict__ C,
             int M, int N, int K, int lda, int ldb, int ldc,
             int zdiv,
             size_t aO, size_t aI, size_t bO, size_t bI, size_t cO, size_t cI)
{
    const int z = blockIdx.z;
    A  += (size_t)(z / zdiv) * aO + (size_t)(z % zdiv) * aI;
    Bm += (size_t)(z / zdiv) * bO + (size_t)(z % zdiv) * bI;
    C  += (size_t)(z / zdiv) * cO + (size_t)(z % zdiv) * cI;

    __shared__ float As[16][132];
    __shared__ float Bs[16][132];

    const int tid = threadIdx.x;
    const int tx  = tid & 15;
    const int ty  = tid >> 4;
    const int m0  = blockIdx.y * 128;
    const int n0  = blockIdx.x * 128;

    float acc[8][8];
#pragma unroll
    for (int i = 0; i < 8; i++)
#pragma unroll
        for (int j = 0; j < 8; j++) acc[i][j] = 0.0f;

    for (int k0 = 0; k0 < K; k0 += 16) {
        {
            const int r  = tid >> 2;
            const int kq = (tid & 3) * 4;
#pragma unroll
            for (int half = 0; half < 2; half++) {
                const int row = r + half * 64;
                const int gm  = m0 + row;
                float4 v = make_float4(0.f, 0.f, 0.f, 0.f);
                if (gm < M)
                    v = *(const float4*)(A + (size_t)gm * lda + k0 + kq);
                As[kq + 0][row] = v.x; As[kq + 1][row] = v.y;
                As[kq + 2][row] = v.z; As[kq + 3][row] = v.w;
            }
        }
        if (BT) {
            const int r  = tid >> 2;
            const int kq = (tid & 3) * 4;
#pragma unroll
            for (int half = 0; half < 2; half++) {
                const int row = r + half * 64;
                const int gn  = n0 + row;
                float4 v = make_float4(0.f, 0.f, 0.f, 0.f);
                if (gn < N)
                    v = *(const float4*)(Bm + (size_t)gn * ldb + k0 + kq);
                Bs[kq + 0][row] = v.x; Bs[kq + 1][row] = v.y;
                Bs[kq + 2][row] = v.z; Bs[kq + 3][row] = v.w;
            }
        } else {
            const int kr = tid >> 4;
            const int nq = (tid & 15) * 4;
#pragma unroll
            for (int half = 0; half < 2; half++) {
                const int col = nq + half * 64;
                const int gn  = n0 + col;
                float4 v = make_float4(0.f, 0.f, 0.f, 0.f);
                if (gn < N)
                    v = *(const float4*)(Bm + (size_t)(k0 + kr) * ldb + gn);
                Bs[kr][col + 0] = v.x; Bs[kr][col + 1] = v.y;
                Bs[kr][col + 2] = v.z; Bs[kr][col + 3] = v.w;
            }
        }
        __syncthreads();

#pragma unroll
        for (int kk = 0; kk < 16; kk++) {
            float a[8], b[8];
            *(float4*)&a[0] = *(const float4*)&As[kk][ty * 4];
            *(float4*)&a[4] = *(const float4*)&As[kk][64 + ty * 4];
            *(float4*)&b[0] = *(const float4*)&Bs[kk][tx * 4];
            *(float4*)&b[4] = *(const float4*)&Bs[kk][64 + tx * 4];
#pragma unroll
            for (int i = 0; i < 8; i++)
#pragma unroll
                for (int j = 0; j < 8; j++)
                    acc[i][j] = fmaf(a[i], b[j], acc[i][j]);
        }
        __syncthreads();
    }

#pragma unroll
    for (int i = 0; i < 8; i++) {
        const int lm = (i < 4) ? (ty * 4 + i) : (64 + ty * 4 + i - 4);
        const int gm = m0 + lm;
        if (gm >= M) continue;
#pragma unroll
        for (int j = 0; j < 8; j++) {
            const int ln = (j < 4) ? (tx * 4 + j) : (64 + tx * 4 + j - 4);
            const int gn = n0 + ln;
            if (gn >= N) continue;
            float r = acc[i][j];
            if (BIAS) r += bias[gn];
            C[(size_t)gm * ldc + gn] = r;
        }
    }
}

// ---------------- scores v2: 128x128 tile, K-major smem, 8x8 microtile ----------------
// X[b,h,q,k] = mask ? 0 : (scale*qh.kh + bias) -> bf16 hi/lo
#define SC_SMEM (2 * 64 * 132 * 4)

__global__ __launch_bounds__(256)
void scores_kernel(const float* __restrict__ qhp, const float* __restrict__ khp,
                   const float* __restrict__ attn_bias, const uint4* __restrict__ mask,
                   __nv_bfloat16* __restrict__ Xh, __nv_bfloat16* __restrict__ Xl)
{
    extern __shared__ char smemraw[];
    float (*qs)[132] = (float (*)[132])smemraw;
    float (*ks)[132] = (float (*)[132])(smemraw + 64 * 132 * 4);

    const int bh = blockIdx.z;
    const int b  = bh >> 3;
    const int h  = bh & 7;
    const int q0 = blockIdx.y * 128;
    const int k0 = blockIdx.x * 128;

    const int tid = threadIdx.x;
    // load 128 rows x 64 d for q and k, transposed into [d][m]
    {
        const int m  = tid >> 1;
        const int d0 = (tid & 1) * 32;
        const float* qrow = qhp + (size_t)(b * SS + q0 + m) * HID + h * DD + d0;
        const float* krow = khp + (size_t)(b * SS + k0 + m) * HID + h * DD + d0;
#pragma unroll
        for (int c = 0; c < 8; c++) {
            float4 v = *(const float4*)(qrow + c * 4);
            qs[d0 + c * 4 + 0][m] = v.x; qs[d0 + c * 4 + 1][m] = v.y;
            qs[d0 + c * 4 + 2][m] = v.z; qs[d0 + c * 4 + 3][m] = v.w;
            v = *(const float4*)(krow + c * 4);
            ks[d0 + c * 4 + 0][m] = v.x; ks[d0 + c * 4 + 1][m] = v.y;
            ks[d0 + c * 4 + 2][m] = v.z; ks[d0 + c * 4 + 3][m] = v.w;
        }
    }
    __syncthreads();

    const int tx = tid & 15;
    const int ty = tid >> 4;
    float acc[8][8];
#pragma unroll
    for (int i = 0; i < 8; i++)
#pragma unroll
        for (int j = 0; j < 8; j++) acc[i][j] = 0.0f;

#pragma unroll 4
    for (int d = 0; d < 64; d++) {
        float a[8], bv[8];
        *(float4*)&a[0]  = *(const float4*)&qs[d][ty * 4];
        *(float4*)&a[4]  = *(const float4*)&qs[d][64 + ty * 4];
        *(float4*)&bv[0] = *(const float4*)&ks[d][tx * 4];
        *(float4*)&bv[4] = *(const float4*)&ks[d][64 + tx * 4];
#pragma unroll
        for (int i = 0; i < 8; i++)
#pragma unroll
            for (int j = 0; j < 8; j++)
                acc[i][j] = fmaf(a[i], bv[j], acc[i][j]);
    }

    const float scale = 0.125f;
#pragma unroll
    for (int i = 0; i < 8; i++) {
        const int gq = q0 + ((i < 4) ? (ty * 4 + i) : (64 + ty * 4 + i - 4));
        const size_t mrow = ((size_t)b * SS + gq) * SS;
        const size_t xrow = ((size_t)bh * SS + gq) * SS;
        const size_t brow = xrow;   // attn_bias same layout as X
#pragma unroll
        for (int jh = 0; jh < 2; jh++) {
            const int gk = k0 + jh * 64 + tx * 4;
            uint4  mv = mask[(mrow + gk) >> 2];
            float4 bb = *(const float4*)(attn_bias + brow + gk);
            const float* ac = &acc[i][jh * 4];
            float v0 = mv.x ? 0.0f : fmaf(scale, ac[0], bb.x);
            float v1 = mv.y ? 0.0f : fmaf(scale, ac[1], bb.y);
            float v2 = mv.z ? 0.0f : fmaf(scale, ac[2], bb.z);
            float v3 = mv.w ? 0.0f : fmaf(scale, ac[3], bb.w);
            __nv_bfloat16 h0 = __float2bfloat16(v0), h1 = __float2bfloat16(v1);
            __nv_bfloat16 h2 = __float2bfloat16(v2), h3 = __float2bfloat16(v3);
            __nv_bfloat16 l0 = __float2bfloat16(v0 - __bfloat162float(h0));
            __nv_bfloat16 l1 = __float2bfloat16(v1 - __bfloat162float(h1));
            __nv_bfloat16 l2 = __float2bfloat16(v2 - __bfloat162float(h2));
            __nv_bfloat16 l3 = __float2bfloat16(v3 - __bfloat162float(h3));
            __nv_bfloat162 hp0 = __nv_bfloat162(h0, h1), hp1 = __nv_bfloat162(h2, h3);
            __nv_bfloat162 lp0 = __nv_bfloat162(l0, l1), lp1 = __nv_bfloat162(l2, l3);
            uint2 hv = make_uint2(*(uint32_t*)&hp0, *(uint32_t*)&hp1);
            uint2 lv = make_uint2(*(uint32_t*)&lp0, *(uint32_t*)&lp1);
            *(uint2*)(Xh + xrow + gk) = hv;
            *(uint2*)(Xl + xrow + gk) = lv;
        }
    }
}

// ---------------- softmax over last dim (row length 2048), in-place ----------------
__global__ __launch_bounds__(256)
void softmax_kernel(float* __restrict__ Y)
{
    float* p = Y + (size_t)blockIdx.x * SS;
    const int tid = threadIdx.x;

    float v[8];
    float mx = -1e30f;
#pragma unroll
    for (int i = 0; i < 8; i++) {
        v[i] = p[tid + i * 256];
        mx = fmaxf(mx, v[i]);
    }
    __shared__ float sh[8];
#pragma unroll
    for (int o = 16; o > 0; o >>= 1) mx = fmaxf(mx, __shfl_xor_sync(0xffffffffu, mx, o));
    if ((tid & 31) == 0) sh[tid >> 5] = mx;
    __syncthreads();
    float bm = sh[0];
#pragma unroll
    for (int i = 1; i < 8; i++) bm = fmaxf(bm, sh[i]);
    __syncthreads();

    float sum = 0.0f;
#pragma unroll
    for (int i = 0; i < 8; i++) {
        v[i] = expf(v[i] - bm);
        sum += v[i];
    }
#pragma unroll
    for (int o = 16; o > 0; o >>= 1) sum += __shfl_xor_sync(0xffffffffu, sum, o);
    if ((tid & 31) == 0) sh[tid >> 5] = sum;
    __syncthreads();
    float bs = 0.0f;
#pragma unroll
    for (int i = 0; i < 8; i++) bs += sh[i];
    const float inv = 1.0f / bs;
#pragma unroll
    for (int i = 0; i < 8; i++) p[tid + i * 256] = v[i] * inv;
}

// ---------------- launch ----------------
extern "C" void kernel_launch(void* const* d_in, const int* in_sizes, int n_in,
                              void* d_out, int out_size)
{
    const float*    q    = (const float*)d_in[0];
    const float*    k    = (const float*)d_in[1];
    const float*    v    = (const float*)d_in[2];
    const float*    bias = (const float*)d_in[3];
    const uint4*    mask = (const uint4*)d_in[4];
    const float*    w    = (const float*)d_in[5];
    const float*    Wq   = (const float*)d_in[6];
    const float*    bq   = (const float*)d_in[7];
    const float*    Wk   = (const float*)d_in[8];
    const float*    bk   = (const float*)d_in[9];
    const float*    Wv   = (const float*)d_in[10];
    const float*    bv   = (const float*)d_in[11];
    const float*    Wo   = (const float*)d_in[12];
    const float*    bo   = (const float*)d_in[13];
    float* out = (float*)d_out;

    float *qh, *kh, *vh, *Y, *O;
    __nv_bfloat16 *Xh, *Xl, *whT, *wlT;
    cudaGetSymbolAddress((void**)&qh,  g_qh);
    cudaGetSymbolAddress((void**)&kh,  g_kh);
    cudaGetSymbolAddress((void**)&vh,  g_vh);
    cudaGetSymbolAddress((void**)&Y,   g_Y);
    cudaGetSymbolAddress((void**)&O,   g_O);
    cudaGetSymbolAddress((void**)&Xh,  g_Xh);
    cudaGetSymbolAddress((void**)&Xl,  g_Xl);
    cudaGetSymbolAddress((void**)&whT, g_whT);
    cudaGetSymbolAddress((void**)&wlT, g_wlT);

    cudaFuncSetAttribute(xw_mma_kernel, cudaFuncAttributeMaxDynamicSharedMemorySize, XW_SMEM);
    cudaFuncSetAttribute(scores_kernel, cudaFuncAttributeMaxDynamicSharedMemorySize, SC_SMEM);

    const size_t SSs = (size_t)SS * SS;

    // 0) w -> bf16 hi/lo transposed
    {
        dim3 grid(SS / 32, SS / 32, BB);
        convw_kernel<<<grid, 256>>>(w, whT, wlT);
    }

    // 1) QKV projections
    {
        dim3 grid(HID / 128, (BB * SS) / 128, 1);
        gemm128<true, true><<<grid, 256>>>(q, Wq, bq, qh,
            BB * SS, HID, HID, HID, HID, HID, 1, 0, 0, 0, 0, 0, 0);
        gemm128<true, true><<<grid, 256>>>(k, Wk, bk, kh,
            BB * SS, HID, HID, HID, HID, HID, 1, 0, 0, 0, 0, 0, 0);
        gemm128<true, true><<<grid, 256>>>(v, Wv, bv, vh,
            BB * SS, HID, HID, HID, HID, HID, 1, 0, 0, 0, 0, 0, 0);
    }

    // 2) scores + bias + mask -> Xh/Xl bf16
    {
        dim3 grid(SS / 128, SS / 128, BB * NHH);
        scores_kernel<<<grid, 256, SC_SMEM>>>(qh, kh, bias, mask, Xh, Xl);
    }

    // 3) Y = X @ w  via mma.sync bf16 3-term split
    {
        dim3 grid(SS / 128, (BB * NHH * SS) / 256, 1);
        xw_mma_kernel<<<grid, 256, XW_SMEM>>>(Xh, Xl, whT, wlT, Y);
    }

    // 4) softmax rows of Y in-place
    softmax_kernel<<<BB * NHH * SS, 256>>>(Y);

    // 5) O = P @ vh
    {
        dim3 grid(1, SS / 128, BB * NHH);
        gemm128<false, false><<<grid, 256>>>(Y, vh, nullptr, O,
            SS, DD, SS, SS, HID, HID,
            8,
            (size_t)NHH * SSs, SSs,
            (size_t)SS * HID, (size_t)DD,
            (size_t)SS * HID, (size_t)DD);
    }

    // 6) out = O @ Wo^T + bo
    {
        dim3 grid(HID / 128, (BB * SS) / 128, 1);
        gemm128<true, true><<<grid, 256>>>(O, Wo, bo, out,
            BB * SS, HID, HID, HID, HID, HID, 1, 0, 0, 0, 0, 0, 0);
    }
}

// round 8
// speedup vs baseline: 1.4379x; 1.4379x over previous
#include <cuda_runtime.h>
#include <cuda_bf16.h>
#include <cstdint>
#include <math.h>

// Problem dims
#define BB   2
#define SS   2048
#define HID  512
#define NHH  8
#define DD   64

// ---------------- scratch (static device globals; no allocation) ----------------
__device__ float g_qh[(size_t)BB * SS * HID];
__device__ float g_kh[(size_t)BB * SS * HID];
__device__ float g_vh[(size_t)BB * SS * HID];
__device__ __nv_bfloat16 g_Xh[(size_t)BB * NHH * SS * SS];   // hi(bf16) of masked scores
__device__ __nv_bfloat16 g_Xl[(size_t)BB * NHH * SS * SS];   // lo residual
__device__ __nv_bfloat16 g_whT[(size_t)BB * SS * SS];        // w^T bf16  [b][l][k]
__device__ float g_Y [(size_t)BB * NHH * SS * SS];           // X@w, softmax in-place
__device__ float g_O [(size_t)BB * SS * HID];

// ================= helpers =================
__device__ __forceinline__ uint32_t smem_u32(const void* p) {
    uint32_t a;
    asm("{ .reg .u64 t; cvta.to.shared.u64 t, %1; cvt.u32.u64 %0, t; }" : "=r"(a) : "l"(p));
    return a;
}
__device__ __forceinline__ uint32_t sw128(uint32_t o) { return o ^ ((o >> 3) & 0x70); }

__device__ __forceinline__ void ldsm4(uint32_t& r0, uint32_t& r1, uint32_t& r2, uint32_t& r3, uint32_t addr) {
    asm volatile("ldmatrix.sync.aligned.m8n8.x4.shared.b16 {%0,%1,%2,%3}, [%4];"
        : "=r"(r0), "=r"(r1), "=r"(r2), "=r"(r3) : "r"(addr));
}
__device__ __forceinline__ void mma16816(float* d, const uint32_t* a, const uint32_t* b) {
    asm volatile("mma.sync.aligned.m16n8k16.row.col.f32.bf16.bf16.f32 "
        "{%0,%1,%2,%3}, {%4,%5,%6,%7}, {%8,%9}, {%0,%1,%2,%3};"
        : "+f"(d[0]), "+f"(d[1]), "+f"(d[2]), "+f"(d[3])
        : "r"(a[0]), "r"(a[1]), "r"(a[2]), "r"(a[3]), "r"(b[0]), "r"(b[1]));
}
__device__ __forceinline__ void cpa16(uint32_t dst, const void* src) {
    asm volatile("cp.async.cg.shared.global [%0], [%1], 16;" :: "r"(dst), "l"(src));
}

// ================= x@w GEMM via mma.sync bf16 =================
// Y = [Xh | Xl] @ [wh ; wh]  (K = 2*2048, B wraps mod 2048) — 2-term precision.
// CTA 128x128, 8 warps (4m x 2n), warp tile 32x64, K-chunk 64.
// Stage: A 16KB + B 16KB = 32KB; 3 stages = 96KB -> 2 CTAs/SM.
#define XW_STAGE 32768
#define XW_SMEM  (3 * XW_STAGE)
#define XW_NCHUNK 64

__device__ __forceinline__ void xw_load(
    uint32_t sbase, int slot, int chunk,
    const __nv_bfloat16* __restrict__ Xh, const __nv_bfloat16* __restrict__ Xl,
    const __nv_bfloat16* __restrict__ whb,
    int m0, int n0, int tid)
{
    const int kk = (chunk & 31) * 64;
    const __nv_bfloat16* Asrc = (chunk < 32) ? Xh : Xl;
    const uint32_t base = sbase + (uint32_t)slot * XW_STAGE;
    const int row  = tid >> 1;
    const int half = tid & 1;
    const __nv_bfloat16* arow = Asrc + (size_t)(m0 + row) * SS + kk + half * 32;
    const __nv_bfloat16* brow = whb  + (size_t)(n0 + row) * SS + kk + half * 32;
    const uint32_t roff = (uint32_t)row * 128 + (uint32_t)half * 64;
#pragma unroll
    for (int c = 0; c < 4; c++) {
        uint32_t s = sw128(roff + c * 16);
        cpa16(base +         s, arow + c * 8);
        cpa16(base + 16384 + s, brow + c * 8);
    }
}

__device__ __forceinline__ void xw_compute(uint32_t stg, int wm, int wn, int lane,
                                           float acc[2][8][4])
{
    const uint32_t aB = stg, bB = stg + 16384;
    const uint32_t a_base = (uint32_t)(wm * 32 + (lane & 15)) * 128 + (uint32_t)((lane >> 4) * 16);
    const uint32_t b_base = (uint32_t)(wn * 64 + (lane & 7) + ((lane >> 4) << 3)) * 128
                          + (uint32_t)(((lane >> 3) & 1) * 16);
#pragma unroll
    for (int ks = 0; ks < 4; ks++) {
        const uint32_t k0b = (uint32_t)ks * 32;
        uint32_t a[2][4], b[8][2];
#pragma unroll
        for (int mb = 0; mb < 2; mb++) {
            uint32_t s = sw128(a_base + (uint32_t)mb * 2048 + k0b);
            ldsm4(a[mb][0], a[mb][1], a[mb][2], a[mb][3], aB + s);
        }
#pragma unroll
        for (int nb2 = 0; nb2 < 4; nb2++) {
            uint32_t s = sw128(b_base + (uint32_t)nb2 * 2048 + k0b);
            uint32_t r0, r1, r2, r3;
            ldsm4(r0, r1, r2, r3, bB + s);
            b[2 * nb2][0] = r0; b[2 * nb2][1] = r1;
            b[2 * nb2 + 1][0] = r2; b[2 * nb2 + 1][1] = r3;
        }
#pragma unroll
        for (int mb = 0; mb < 2; mb++)
#pragma unroll
            for (int nb = 0; nb < 8; nb++)
                mma16816(acc[mb][nb], a[mb], b[nb]);
    }
}

__global__ __launch_bounds__(256, 2)
void xw_mma_kernel(const __nv_bfloat16* __restrict__ Xh, const __nv_bfloat16* __restrict__ Xl,
                   const __nv_bfloat16* __restrict__ whT, float* __restrict__ Y)
{
    extern __shared__ char smem[];
    const uint32_t sbase = smem_u32(smem);
    const int tid  = threadIdx.x;
    const int wid  = tid >> 5;
    const int lane = tid & 31;
    const int wm   = wid & 3;
    const int wn   = wid >> 2;
    const int n0   = blockIdx.x * 128;
    const int m0   = blockIdx.y * 128;
    const int batch = m0 >> 14;                 // 16384 rows per batch
    const __nv_bfloat16* whb = whT + (size_t)batch * SS * SS;

    float acc[2][8][4];
#pragma unroll
    for (int i = 0; i < 2; i++)
#pragma unroll
        for (int j = 0; j < 8; j++)
#pragma unroll
            for (int r = 0; r < 4; r++) acc[i][j][r] = 0.0f;

    // prologue: 3 stages
#pragma unroll
    for (int j = 0; j < 3; j++) {
        xw_load(sbase, j, j, Xh, Xl, whb, m0, n0, tid);
        asm volatile("cp.async.commit_group;" ::: "memory");
    }

    for (int i = 0; i < XW_NCHUNK; i++) {
        const int s = i % 3;
        asm volatile("cp.async.wait_group 2;" ::: "memory");
        __syncthreads();
        xw_compute(sbase + (uint32_t)s * XW_STAGE, wm, wn, lane, acc);
        __syncthreads();
        if (i + 3 < XW_NCHUNK)
            xw_load(sbase, s, i + 3, Xh, Xl, whb, m0, n0, tid);
        asm volatile("cp.async.commit_group;" ::: "memory");
    }

    // epilogue: store fp32 accumulators
    const int r  = lane >> 2;
    const int c2 = (lane & 3) * 2;
#pragma unroll
    for (int mb = 0; mb < 2; mb++) {
        const int row = m0 + wm * 32 + mb * 16 + r;
#pragma unroll
        for (int nb = 0; nb < 8; nb++) {
            const int col = n0 + wn * 64 + nb * 8 + c2;
            float2 v0 = make_float2(acc[mb][nb][0], acc[mb][nb][1]);
            float2 v1 = make_float2(acc[mb][nb][2], acc[mb][nb][3]);
            *(float2*)(Y + (size_t)row * SS + col)       = v0;
            *(float2*)(Y + (size_t)(row + 8) * SS + col) = v1;
        }
    }
}

// ================= w -> bf16 transpose =================
__global__ __launch_bounds__(256)
void convw_kernel(const float* __restrict__ w, __nv_bfloat16* __restrict__ whT)
{
    __shared__ float t[32][33];
    const int b  = blockIdx.z;
    const int k0 = blockIdx.y * 32;
    const int l0 = blockIdx.x * 32;
    const float* wb = w + (size_t)b * SS * SS;
    const int tx = threadIdx.x & 31;
    const int ty = threadIdx.x >> 5;     // 0..7
#pragma unroll
    for (int i = 0; i < 4; i++)
        t[ty + 8 * i][tx] = wb[(size_t)(k0 + ty + 8 * i) * SS + l0 + tx];
    __syncthreads();
#pragma unroll
    for (int i = 0; i < 4; i++) {
        float v = t[tx][ty + 8 * i];                     // w[b][k0+tx][l0+ty+8i]
        size_t idx = (size_t)b * SS * SS + (size_t)(l0 + ty + 8 * i) * SS + (k0 + tx);
        whT[idx] = __float2bfloat16(v);
    }
}

// ---------------- generic batched fp32 GEMM (projections, PV, out-proj) ----------------
template <bool BT, bool BIAS>
__global__ __launch_bounds__(256)
void gemm128(const float* __restrict__ A, const float* __restrict__ Bm,
             const float* __restrict__ bias, float* __restrict__ C,
             int M, int N, int K, int lda, int ldb, int ldc,
             int zdiv,
             size_t aO, size_t aI, size_t bO, size_t bI, size_t cO, size_t cI)
{
    const int z = blockIdx.z;
    A  += (size_t)(z / zdiv) * aO + (size_t)(z % zdiv) * aI;
    Bm += (size_t)(z / zdiv) * bO + (size_t)(z % zdiv) * bI;
    C  += (size_t)(z / zdiv) * cO + (size_t)(z % zdiv) * cI;

    __shared__ float As[16][132];
    __shared__ float Bs[16][132];

    const int tid = threadIdx.x;
    const int tx  = tid & 15;
    const int ty  = tid >> 4;
    const int m0  = blockIdx.y * 128;
    const int n0  = blockIdx.x * 128;

    float acc[8][8];
#pragma unroll
    for (int i = 0; i < 8; i++)
#pragma unroll
        for (int j = 0; j < 8; j++) acc[i][j] = 0.0f;

    for (int k0 = 0; k0 < K; k0 += 16) {
        {
            const int r  = tid >> 2;
            const int kq = (tid & 3) * 4;
#pragma unroll
            for (int half = 0; half < 2; half++) {
                const int row = r + half * 64;
                const int gm  = m0 + row;
                float4 v = make_float4(0.f, 0.f, 0.f, 0.f);
                if (gm < M)
                    v = *(const float4*)(A + (size_t)gm * lda + k0 + kq);
                As[kq + 0][row] = v.x; As[kq + 1][row] = v.y;
                As[kq + 2][row] = v.z; As[kq + 3][row] = v.w;
            }
        }
        if (BT) {
            const int r  = tid >> 2;
            const int kq = (tid & 3) * 4;
#pragma unroll
            for (int half = 0; half < 2; half++) {
                const int row = r + half * 64;
                const int gn  = n0 + row;
                float4 v = make_float4(0.f, 0.f, 0.f, 0.f);
                if (gn < N)
                    v = *(const float4*)(Bm + (size_t)gn * ldb + k0 + kq);
                Bs[kq + 0][row] = v.x; Bs[kq + 1][row] = v.y;
                Bs[kq + 2][row] = v.z; Bs[kq + 3][row] = v.w;
            }
        } else {
            const int kr = tid >> 4;
            const int nq = (tid & 15) * 4;
#pragma unroll
            for (int half = 0; half < 2; half++) {
                const int col = nq + half * 64;
                const int gn  = n0 + col;
                float4 v = make_float4(0.f, 0.f, 0.f, 0.f);
                if (gn < N)
                    v = *(const float4*)(Bm + (size_t)(k0 + kr) * ldb + gn);
                Bs[kr][col + 0] = v.x; Bs[kr][col + 1] = v.y;
                Bs[kr][col + 2] = v.z; Bs[kr][col + 3] = v.w;
            }
        }
        __syncthreads();

#pragma unroll
        for (int kk = 0; kk < 16; kk++) {
            float a[8], b[8];
            *(float4*)&a[0] = *(const float4*)&As[kk][ty * 4];
            *(float4*)&a[4] = *(const float4*)&As[kk][64 + ty * 4];
            *(float4*)&b[0] = *(const float4*)&Bs[kk][tx * 4];
            *(float4*)&b[4] = *(const float4*)&Bs[kk][64 + tx * 4];
#pragma unroll
            for (int i = 0; i < 8; i++)
#pragma unroll
                for (int j = 0; j < 8; j++)
                    acc[i][j] = fmaf(a[i], b[j], acc[i][j]);
        }
        __syncthreads();
    }

#pragma unroll
    for (int i = 0; i < 8; i++) {
        const int lm = (i < 4) ? (ty * 4 + i) : (64 + ty * 4 + i - 4);
        const int gm = m0 + lm;
        if (gm >= M) continue;
#pragma unroll
        for (int j = 0; j < 8; j++) {
            const int ln = (j < 4) ? (tx * 4 + j) : (64 + tx * 4 + j - 4);
            const int gn = n0 + ln;
            if (gn >= N) continue;
            float r = acc[i][j];
            if (BIAS) r += bias[gn];
            C[(size_t)gm * ldc + gn] = r;
        }
    }
}

// ---------------- scores v2: 128x128 tile, K-major smem, 8x8 microtile ----------------
// X[b,h,q,k] = mask ? 0 : (scale*qh.kh + bias) -> bf16 hi/lo
#define SC_SMEM (2 * 64 * 132 * 4)

__global__ __launch_bounds__(256)
void scores_kernel(const float* __restrict__ qhp, const float* __restrict__ khp,
                   const float* __restrict__ attn_bias, const uint4* __restrict__ mask,
                   __nv_bfloat16* __restrict__ Xh, __nv_bfloat16* __restrict__ Xl)
{
    extern __shared__ char smemraw[];
    float (*qs)[132] = (float (*)[132])smemraw;
    float (*ks)[132] = (float (*)[132])(smemraw + 64 * 132 * 4);

    const int bh = blockIdx.z;
    const int b  = bh >> 3;
    const int h  = bh & 7;
    const int q0 = blockIdx.y * 128;
    const int k0 = blockIdx.x * 128;

    const int tid = threadIdx.x;
    // load 128 rows x 64 d for q and k, transposed into [d][m]
    {
        const int m  = tid >> 1;
        const int d0 = (tid & 1) * 32;
        const float* qrow = qhp + (size_t)(b * SS + q0 + m) * HID + h * DD + d0;
        const float* krow = khp + (size_t)(b * SS + k0 + m) * HID + h * DD + d0;
#pragma unroll
        for (int c = 0; c < 8; c++) {
            float4 v = *(const float4*)(qrow + c * 4);
            qs[d0 + c * 4 + 0][m] = v.x; qs[d0 + c * 4 + 1][m] = v.y;
            qs[d0 + c * 4 + 2][m] = v.z; qs[d0 + c * 4 + 3][m] = v.w;
            v = *(const float4*)(krow + c * 4);
            ks[d0 + c * 4 + 0][m] = v.x; ks[d0 + c * 4 + 1][m] = v.y;
            ks[d0 + c * 4 + 2][m] = v.z; ks[d0 + c * 4 + 3][m] = v.w;
        }
    }
    __syncthreads();

    const int tx = tid & 15;
    const int ty = tid >> 4;
    float acc[8][8];
#pragma unroll
    for (int i = 0; i < 8; i++)
#pragma unroll
        for (int j = 0; j < 8; j++) acc[i][j] = 0.0f;

#pragma unroll 4
    for (int d = 0; d < 64; d++) {
        float a[8], bv[8];
        *(float4*)&a[0]  = *(const float4*)&qs[d][ty * 4];
        *(float4*)&a[4]  = *(const float4*)&qs[d][64 + ty * 4];
        *(float4*)&bv[0] = *(const float4*)&ks[d][tx * 4];
        *(float4*)&bv[4] = *(const float4*)&ks[d][64 + tx * 4];
#pragma unroll
        for (int i = 0; i < 8; i++)
#pragma unroll
            for (int j = 0; j < 8; j++)
                acc[i][j] = fmaf(a[i], bv[j], acc[i][j]);
    }

    const float scale = 0.125f;
#pragma unroll
    for (int i = 0; i < 8; i++) {
        const int gq = q0 + ((i < 4) ? (ty * 4 + i) : (64 + ty * 4 + i - 4));
        const size_t mrow = ((size_t)b * SS + gq) * SS;
        const size_t xrow = ((size_t)bh * SS + gq) * SS;
        const size_t brow = xrow;   // attn_bias same layout as X
#pragma unroll
        for (int jh = 0; jh < 2; jh++) {
            const int gk = k0 + jh * 64 + tx * 4;
            uint4  mv = mask[(mrow + gk) >> 2];
            float4 bb = *(const float4*)(attn_bias + brow + gk);
            const float* ac = &acc[i][jh * 4];
            float v0 = mv.x ? 0.0f : fmaf(scale, ac[0], bb.x);
            float v1 = mv.y ? 0.0f : fmaf(scale, ac[1], bb.y);
            float v2 = mv.z ? 0.0f : fmaf(scale, ac[2], bb.z);
            float v3 = mv.w ? 0.0f : fmaf(scale, ac[3], bb.w);
            __nv_bfloat16 h0 = __float2bfloat16(v0), h1 = __float2bfloat16(v1);
            __nv_bfloat16 h2 = __float2bfloat16(v2), h3 = __float2bfloat16(v3);
            __nv_bfloat16 l0 = __float2bfloat16(v0 - __bfloat162float(h0));
            __nv_bfloat16 l1 = __float2bfloat16(v1 - __bfloat162float(h1));
            __nv_bfloat16 l2 = __float2bfloat16(v2 - __bfloat162float(h2));
            __nv_bfloat16 l3 = __float2bfloat16(v3 - __bfloat162float(h3));
            __nv_bfloat162 hp0 = __nv_bfloat162(h0, h1), hp1 = __nv_bfloat162(h2, h3);
            __nv_bfloat162 lp0 = __nv_bfloat162(l0, l1), lp1 = __nv_bfloat162(l2, l3);
            uint2 hv = make_uint2(*(uint32_t*)&hp0, *(uint32_t*)&hp1);
            uint2 lv = make_uint2(*(uint32_t*)&lp0, *(uint32_t*)&lp1);
            *(uint2*)(Xh + xrow + gk) = hv;
            *(uint2*)(Xl + xrow + gk) = lv;
        }
    }
}

// ---------------- softmax over last dim (row length 2048), in-place ----------------
__global__ __launch_bounds__(256)
void softmax_kernel(float* __restrict__ Y)
{
    float* p = Y + (size_t)blockIdx.x * SS;
    const int tid = threadIdx.x;

    float v[8];
    float mx = -1e30f;
#pragma unroll
    for (int i = 0; i < 8; i++) {
        v[i] = p[tid + i * 256];
        mx = fmaxf(mx, v[i]);
    }
    __shared__ float sh[8];
#pragma unroll
    for (int o = 16; o > 0; o >>= 1) mx = fmaxf(mx, __shfl_xor_sync(0xffffffffu, mx, o));
    if ((tid & 31) == 0) sh[tid >> 5] = mx;
    __syncthreads();
    float bm = sh[0];
#pragma unroll
    for (int i = 1; i < 8; i++) bm = fmaxf(bm, sh[i]);
    __syncthreads();

    float sum = 0.0f;
#pragma unroll
    for (int i = 0; i < 8; i++) {
        v[i] = expf(v[i] - bm);
        sum += v[i];
    }
#pragma unroll
    for (int o = 16; o > 0; o >>= 1) sum += __shfl_xor_sync(0xffffffffu, sum, o);
    if ((tid & 31) == 0) sh[tid >> 5] = sum;
    __syncthreads();
    float bs = 0.0f;
#pragma unroll
    for (int i = 0; i < 8; i++) bs += sh[i];
    const float inv = 1.0f / bs;
#pragma unroll
    for (int i = 0; i < 8; i++) p[tid + i * 256] = v[i] * inv;
}

// ---------------- launch ----------------
extern "C" void kernel_launch(void* const* d_in, const int* in_sizes, int n_in,
                              void* d_out, int out_size)
{
    const float*    q    = (const float*)d_in[0];
    const float*    k    = (const float*)d_in[1];
    const float*    v    = (const float*)d_in[2];
    const float*    bias = (const float*)d_in[3];
    const uint4*    mask = (const uint4*)d_in[4];
    const float*    w    = (const float*)d_in[5];
    const float*    Wq   = (const float*)d_in[6];
    const float*    bq   = (const float*)d_in[7];
    const float*    Wk   = (const float*)d_in[8];
    const float*    bk   = (const float*)d_in[9];
    const float*    Wv   = (const float*)d_in[10];
    const float*    bv   = (const float*)d_in[11];
    const float*    Wo   = (const float*)d_in[12];
    const float*    bo   = (const float*)d_in[13];
    float* out = (float*)d_out;

    float *qh, *kh, *vh, *Y, *O;
    __nv_bfloat16 *Xh, *Xl, *whT;
    cudaGetSymbolAddress((void**)&qh,  g_qh);
    cudaGetSymbolAddress((void**)&kh,  g_kh);
    cudaGetSymbolAddress((void**)&vh,  g_vh);
    cudaGetSymbolAddress((void**)&Y,   g_Y);
    cudaGetSymbolAddress((void**)&O,   g_O);
    cudaGetSymbolAddress((void**)&Xh,  g_Xh);
    cudaGetSymbolAddress((void**)&Xl,  g_Xl);
    cudaGetSymbolAddress((void**)&whT, g_whT);

    cudaFuncSetAttribute(xw_mma_kernel, cudaFuncAttributeMaxDynamicSharedMemorySize, XW_SMEM);
    cudaFuncSetAttribute(scores_kernel, cudaFuncAttributeMaxDynamicSharedMemorySize, SC_SMEM);

    const size_t SSs = (size_t)SS * SS;

    // 0) w -> bf16 transposed
    {
        dim3 grid(SS / 32, SS / 32, BB);
        convw_kernel<<<grid, 256>>>(w, whT);
    }

    // 1) QKV projections
    {
        dim3 grid(HID / 128, (BB * SS) / 128, 1);
        gemm128<true, true><<<grid, 256>>>(q, Wq, bq, qh,
            BB * SS, HID, HID, HID, HID, HID, 1, 0, 0, 0, 0, 0, 0);
        gemm128<true, true><<<grid, 256>>>(k, Wk, bk, kh,
            BB * SS, HID, HID, HID, HID, HID, 1, 0, 0, 0, 0, 0, 0);
        gemm128<true, true><<<grid, 256>>>(v, Wv, bv, vh,
            BB * SS, HID, HID, HID, HID, HID, 1, 0, 0, 0, 0, 0, 0);
    }

    // 2) scores + bias + mask -> Xh/Xl bf16
    {
        dim3 grid(SS / 128, SS / 128, BB * NHH);
        scores_kernel<<<grid, 256, SC_SMEM>>>(qh, kh, bias, mask, Xh, Xl);
    }

    // 3) Y = X @ w  via mma.sync bf16, K-concatenated 2-term
    {
        dim3 grid(SS / 128, (BB * NHH * SS) / 128, 1);
        xw_mma_kernel<<<grid, 256, XW_SMEM>>>(Xh, Xl, whT, Y);
    }

    // 4) softmax rows of Y in-place
    softmax_kernel<<<BB * NHH * SS, 256>>>(Y);

    // 5) O = P @ vh
    {
        dim3 grid(1, SS / 128, BB * NHH);
        gemm128<false, false><<<grid, 256>>>(Y, vh, nullptr, O,
            SS, DD, SS, SS, HID, HID,
            8,
            (size_t)NHH * SSs, SSs,
            (size_t)SS * HID, (size_t)DD,
            (size_t)SS * HID, (size_t)DD);
    }

    // 6) out = O @ Wo^T + bo
    {
        dim3 grid(HID / 128, (BB * SS) / 128, 1);
        gemm128<true, true><<<grid, 256>>>(O, Wo, bo, out,
            BB * SS, HID, HID, HID, HID, HID, 1, 0, 0, 0, 0, 0, 0);
    }
}

// round 9
// speedup vs baseline: 3.3685x; 2.3426x over previous
#include <cuda_runtime.h>
#include <cuda_bf16.h>
#include <cstdint>
#include <math.h>

// Problem dims
#define BB   2
#define SS   2048
#define HID  512
#define NHH  8
#define DD   64

// ---------------- scratch (static device globals; no allocation) ----------------
__device__ float g_qh[(size_t)BB * SS * HID];
__device__ float g_kh[(size_t)BB * SS * HID];
__device__ float g_vh[(size_t)BB * SS * HID];
__device__ __nv_bfloat16 g_Xh[(size_t)BB * NHH * SS * SS];   // bf16 masked scores
__device__ __nv_bfloat16 g_whT[(size_t)BB * SS * SS];        // w^T bf16  [b][l][k]
__device__ float g_Y [(size_t)BB * NHH * SS * SS];           // X@w, softmax in-place
__device__ float g_O [(size_t)BB * SS * HID];

// ================= helpers =================
__device__ __forceinline__ uint32_t smem_u32(const void* p) {
    uint32_t a;
    asm("{ .reg .u64 t; cvta.to.shared.u64 t, %1; cvt.u32.u64 %0, t; }" : "=r"(a) : "l"(p));
    return a;
}
__device__ __forceinline__ uint32_t sw128(uint32_t o) { return o ^ ((o >> 3) & 0x70); }

__device__ __forceinline__ void ldsm4(uint32_t& r0, uint32_t& r1, uint32_t& r2, uint32_t& r3, uint32_t addr) {
    asm volatile("ldmatrix.sync.aligned.m8n8.x4.shared.b16 {%0,%1,%2,%3}, [%4];"
        : "=r"(r0), "=r"(r1), "=r"(r2), "=r"(r3) : "r"(addr));
}
__device__ __forceinline__ void mma16816(float* d, const uint32_t* a, const uint32_t* b) {
    asm volatile("mma.sync.aligned.m16n8k16.row.col.f32.bf16.bf16.f32 "
        "{%0,%1,%2,%3}, {%4,%5,%6,%7}, {%8,%9}, {%0,%1,%2,%3};"
        : "+f"(d[0]), "+f"(d[1]), "+f"(d[2]), "+f"(d[3])
        : "r"(a[0]), "r"(a[1]), "r"(a[2]), "r"(a[3]), "r"(b[0]), "r"(b[1]));
}
__device__ __forceinline__ void cpa16(uint32_t dst, const void* src) {
    asm volatile("cp.async.cg.shared.global [%0], [%1], 16;" :: "r"(dst), "l"(src));
}

// ================= x@w GEMM via mma.sync bf16 =================
// Y = Xh @ whT'  (plain bf16 GEMM, K=2048), fp32 accum.
// CTA 128x128, 8 warps (4m x 2n), warp tile 32x64, K-chunk 64.
// Stage: A 16KB + B 16KB = 32KB; 3 stages = 96KB -> 2 CTAs/SM.
#define XW_STAGE 32768
#define XW_SMEM  (3 * XW_STAGE)
#define XW_NCHUNK 32

__device__ __forceinline__ void xw_load(
    uint32_t sbase, int slot, int chunk,
    const __nv_bfloat16* __restrict__ Xh,
    const __nv_bfloat16* __restrict__ whb,
    int m0, int n0, int tid)
{
    const int kk = chunk * 64;
    const uint32_t base = sbase + (uint32_t)slot * XW_STAGE;
    const int row  = tid >> 1;
    const int half = tid & 1;
    const __nv_bfloat16* arow = Xh  + (size_t)(m0 + row) * SS + kk + half * 32;
    const __nv_bfloat16* brow = whb + (size_t)(n0 + row) * SS + kk + half * 32;
    const uint32_t roff = (uint32_t)row * 128 + (uint32_t)half * 64;
#pragma unroll
    for (int c = 0; c < 4; c++) {
        uint32_t s = sw128(roff + c * 16);
        cpa16(base +         s, arow + c * 8);
        cpa16(base + 16384 + s, brow + c * 8);
    }
}

__device__ __forceinline__ void xw_compute(uint32_t stg, int wm, int wn, int lane,
                                           float acc[2][8][4])
{
    const uint32_t aB = stg, bB = stg + 16384;
    const uint32_t a_base = (uint32_t)(wm * 32 + (lane & 15)) * 128 + (uint32_t)((lane >> 4) * 16);
    const uint32_t b_base = (uint32_t)(wn * 64 + (lane & 7) + ((lane >> 4) << 3)) * 128
                          + (uint32_t)(((lane >> 3) & 1) * 16);
#pragma unroll
    for (int ks = 0; ks < 4; ks++) {
        const uint32_t k0b = (uint32_t)ks * 32;
        uint32_t a[2][4], b[8][2];
#pragma unroll
        for (int mb = 0; mb < 2; mb++) {
            uint32_t s = sw128(a_base + (uint32_t)mb * 2048 + k0b);
            ldsm4(a[mb][0], a[mb][1], a[mb][2], a[mb][3], aB + s);
        }
#pragma unroll
        for (int nb2 = 0; nb2 < 4; nb2++) {
            uint32_t s = sw128(b_base + (uint32_t)nb2 * 2048 + k0b);
            uint32_t r0, r1, r2, r3;
            ldsm4(r0, r1, r2, r3, bB + s);
            b[2 * nb2][0] = r0; b[2 * nb2][1] = r1;
            b[2 * nb2 + 1][0] = r2; b[2 * nb2 + 1][1] = r3;
        }
#pragma unroll
        for (int mb = 0; mb < 2; mb++)
#pragma unroll
            for (int nb = 0; nb < 8; nb++)
                mma16816(acc[mb][nb], a[mb], b[nb]);
    }
}

__global__ __launch_bounds__(256, 2)
void xw_mma_kernel(const __nv_bfloat16* __restrict__ Xh,
                   const __nv_bfloat16* __restrict__ whT, float* __restrict__ Y)
{
    extern __shared__ char smem[];
    const uint32_t sbase = smem_u32(smem);
    const int tid  = threadIdx.x;
    const int wid  = tid >> 5;
    const int lane = tid & 31;
    const int wm   = wid & 3;
    const int wn   = wid >> 2;
    const int n0   = blockIdx.x * 128;
    const int m0   = blockIdx.y * 128;
    const int batch = m0 >> 14;                 // 16384 rows per batch
    const __nv_bfloat16* whb = whT + (size_t)batch * SS * SS;

    float acc[2][8][4];
#pragma unroll
    for (int i = 0; i < 2; i++)
#pragma unroll
        for (int j = 0; j < 8; j++)
#pragma unroll
            for (int r = 0; r < 4; r++) acc[i][j][r] = 0.0f;

    // prologue: 3 stages
#pragma unroll
    for (int j = 0; j < 3; j++) {
        xw_load(sbase, j, j, Xh, whb, m0, n0, tid);
        asm volatile("cp.async.commit_group;" ::: "memory");
    }

    for (int i = 0; i < XW_NCHUNK; i++) {
        const int s = i % 3;
        asm volatile("cp.async.wait_group 2;" ::: "memory");
        __syncthreads();
        xw_compute(sbase + (uint32_t)s * XW_STAGE, wm, wn, lane, acc);
        __syncthreads();
        if (i + 3 < XW_NCHUNK)
            xw_load(sbase, s, i + 3, Xh, whb, m0, n0, tid);
        asm volatile("cp.async.commit_group;" ::: "memory");
    }

    // epilogue: store fp32 accumulators
    const int r  = lane >> 2;
    const int c2 = (lane & 3) * 2;
#pragma unroll
    for (int mb = 0; mb < 2; mb++) {
        const int row = m0 + wm * 32 + mb * 16 + r;
#pragma unroll
        for (int nb = 0; nb < 8; nb++) {
            const int col = n0 + wn * 64 + nb * 8 + c2;
            float2 v0 = make_float2(acc[mb][nb][0], acc[mb][nb][1]);
            float2 v1 = make_float2(acc[mb][nb][2], acc[mb][nb][3]);
            *(float2*)(Y + (size_t)row * SS + col)       = v0;
            *(float2*)(Y + (size_t)(row + 8) * SS + col) = v1;
        }
    }
}

// ================= w -> bf16 transpose =================
__global__ __launch_bounds__(256)
void convw_kernel(const float* __restrict__ w, __nv_bfloat16* __restrict__ whT)
{
    __shared__ float t[32][33];
    const int b  = blockIdx.z;
    const int k0 = blockIdx.y * 32;
    const int l0 = blockIdx.x * 32;
    const float* wb = w + (size_t)b * SS * SS;
    const int tx = threadIdx.x & 31;
    const int ty = threadIdx.x >> 5;     // 0..7
#pragma unroll
    for (int i = 0; i < 4; i++)
        t[ty + 8 * i][tx] = wb[(size_t)(k0 + ty + 8 * i) * SS + l0 + tx];
    __syncthreads();
#pragma unroll
    for (int i = 0; i < 4; i++) {
        float v = t[tx][ty + 8 * i];                     // w[b][k0+tx][l0+ty+8i]
        size_t idx = (size_t)b * SS * SS + (size_t)(l0 + ty + 8 * i) * SS + (k0 + tx);
        whT[idx] = __float2bfloat16(v);
    }
}

// ---------------- generic batched fp32 GEMM (projections, PV, out-proj) ----------------
template <bool BT, bool BIAS>
__global__ __launch_bounds__(256)
void gemm128(const float* __restrict__ A, const float* __restrict__ Bm,
             const float* __restrict__ bias, float* __restrict__ C,
             int M, int N, int K, int lda, int ldb, int ldc,
             int zdiv,
             size_t aO, size_t aI, size_t bO, size_t bI, size_t cO, size_t cI)
{
    const int z = blockIdx.z;
    A  += (size_t)(z / zdiv) * aO + (size_t)(z % zdiv) * aI;
    Bm += (size_t)(z / zdiv) * bO + (size_t)(z % zdiv) * bI;
    C  += (size_t)(z / zdiv) * cO + (size_t)(z % zdiv) * cI;

    __shared__ float As[16][132];
    __shared__ float Bs[16][132];

    const int tid = threadIdx.x;
    const int tx  = tid & 15;
    const int ty  = tid >> 4;
    const int m0  = blockIdx.y * 128;
    const int n0  = blockIdx.x * 128;

    float acc[8][8];
#pragma unroll
    for (int i = 0; i < 8; i++)
#pragma unroll
        for (int j = 0; j < 8; j++) acc[i][j] = 0.0f;

    for (int k0 = 0; k0 < K; k0 += 16) {
        {
            const int r  = tid >> 2;
            const int kq = (tid & 3) * 4;
#pragma unroll
            for (int half = 0; half < 2; half++) {
                const int row = r + half * 64;
                const int gm  = m0 + row;
                float4 v = make_float4(0.f, 0.f, 0.f, 0.f);
                if (gm < M)
                    v = *(const float4*)(A + (size_t)gm * lda + k0 + kq);
                As[kq + 0][row] = v.x; As[kq + 1][row] = v.y;
                As[kq + 2][row] = v.z; As[kq + 3][row] = v.w;
            }
        }
        if (BT) {
            const int r  = tid >> 2;
            const int kq = (tid & 3) * 4;
#pragma unroll
            for (int half = 0; half < 2; half++) {
                const int row = r + half * 64;
                const int gn  = n0 + row;
                float4 v = make_float4(0.f, 0.f, 0.f, 0.f);
                if (gn < N)
                    v = *(const float4*)(Bm + (size_t)gn * ldb + k0 + kq);
                Bs[kq + 0][row] = v.x; Bs[kq + 1][row] = v.y;
                Bs[kq + 2][row] = v.z; Bs[kq + 3][row] = v.w;
            }
        } else {
            const int kr = tid >> 4;
            const int nq = (tid & 15) * 4;
#pragma unroll
            for (int half = 0; half < 2; half++) {
                const int col = nq + half * 64;
                const int gn  = n0 + col;
                float4 v = make_float4(0.f, 0.f, 0.f, 0.f);
                if (gn < N)
                    v = *(const float4*)(Bm + (size_t)(k0 + kr) * ldb + gn);
                Bs[kr][col + 0] = v.x; Bs[kr][col + 1] = v.y;
                Bs[kr][col + 2] = v.z; Bs[kr][col + 3] = v.w;
            }
        }
        __syncthreads();

#pragma unroll
        for (int kk = 0; kk < 16; kk++) {
            float a[8], b[8];
            *(float4*)&a[0] = *(const float4*)&As[kk][ty * 4];
            *(float4*)&a[4] = *(const float4*)&As[kk][64 + ty * 4];
            *(float4*)&b[0] = *(const float4*)&Bs[kk][tx * 4];
            *(float4*)&b[4] = *(const float4*)&Bs[kk][64 + tx * 4];
#pragma unroll
            for (int i = 0; i < 8; i++)
#pragma unroll
                for (int j = 0; j < 8; j++)
                    acc[i][j] = fmaf(a[i], b[j], acc[i][j]);
        }
        __syncthreads();
    }

#pragma unroll
    for (int i = 0; i < 8; i++) {
        const int lm = (i < 4) ? (ty * 4 + i) : (64 + ty * 4 + i - 4);
        const int gm = m0 + lm;
        if (gm >= M) continue;
#pragma unroll
        for (int j = 0; j < 8; j++) {
            const int ln = (j < 4) ? (tx * 4 + j) : (64 + tx * 4 + j - 4);
            const int gn = n0 + ln;
            if (gn >= N) continue;
            float r = acc[i][j];
            if (BIAS) r += bias[gn];
            C[(size_t)gm * ldc + gn] = r;
        }
    }
}

// ---------------- scores: 128x128 tile, K-major smem, 8x8 microtile ----------------
// X[b,h,q,k] = mask ? 0 : (scale*qh.kh + bias) -> bf16
#define SC_SMEM (2 * 64 * 132 * 4)

__global__ __launch_bounds__(256)
void scores_kernel(const float* __restrict__ qhp, const float* __restrict__ khp,
                   const float* __restrict__ attn_bias, const uint4* __restrict__ mask,
                   __nv_bfloat16* __restrict__ Xh)
{
    extern __shared__ char smemraw[];
    float (*qs)[132] = (float (*)[132])smemraw;
    float (*ks)[132] = (float (*)[132])(smemraw + 64 * 132 * 4);

    const int bh = blockIdx.z;
    const int b  = bh >> 3;
    const int h  = bh & 7;
    const int q0 = blockIdx.y * 128;
    const int k0 = blockIdx.x * 128;

    const int tid = threadIdx.x;
    // load 128 rows x 64 d for q and k, transposed into [d][m]
    {
        const int m  = tid >> 1;
        const int d0 = (tid & 1) * 32;
        const float* qrow = qhp + (size_t)(b * SS + q0 + m) * HID + h * DD + d0;
        const float* krow = khp + (size_t)(b * SS + k0 + m) * HID + h * DD + d0;
#pragma unroll
        for (int c = 0; c < 8; c++) {
            float4 v = *(const float4*)(qrow + c * 4);
            qs[d0 + c * 4 + 0][m] = v.x; qs[d0 + c * 4 + 1][m] = v.y;
            qs[d0 + c * 4 + 2][m] = v.z; qs[d0 + c * 4 + 3][m] = v.w;
            v = *(const float4*)(krow + c * 4);
            ks[d0 + c * 4 + 0][m] = v.x; ks[d0 + c * 4 + 1][m] = v.y;
            ks[d0 + c * 4 + 2][m] = v.z; ks[d0 + c * 4 + 3][m] = v.w;
        }
    }
    __syncthreads();

    const int tx = tid & 15;
    const int ty = tid >> 4;
    float acc[8][8];
#pragma unroll
    for (int i = 0; i < 8; i++)
#pragma unroll
        for (int j = 0; j < 8; j++) acc[i][j] = 0.0f;

#pragma unroll 4
    for (int d = 0; d < 64; d++) {
        float a[8], bv[8];
        *(float4*)&a[0]  = *(const float4*)&qs[d][ty * 4];
        *(float4*)&a[4]  = *(const float4*)&qs[d][64 + ty * 4];
        *(float4*)&bv[0] = *(const float4*)&ks[d][tx * 4];
        *(float4*)&bv[4] = *(const float4*)&ks[d][64 + tx * 4];
#pragma unroll
        for (int i = 0; i < 8; i++)
#pragma unroll
            for (int j = 0; j < 8; j++)
                acc[i][j] = fmaf(a[i], bv[j], acc[i][j]);
    }

    const float scale = 0.125f;
#pragma unroll
    for (int i = 0; i < 8; i++) {
        const int gq = q0 + ((i < 4) ? (ty * 4 + i) : (64 + ty * 4 + i - 4));
        const size_t mrow = ((size_t)b * SS + gq) * SS;
        const size_t xrow = ((size_t)bh * SS + gq) * SS;
#pragma unroll
        for (int jh = 0; jh < 2; jh++) {
            const int gk = k0 + jh * 64 + tx * 4;
            uint4  mv = mask[(mrow + gk) >> 2];
            float4 bb = *(const float4*)(attn_bias + xrow + gk);
            const float* ac = &acc[i][jh * 4];
            float v0 = mv.x ? 0.0f : fmaf(scale, ac[0], bb.x);
            float v1 = mv.y ? 0.0f : fmaf(scale, ac[1], bb.y);
            float v2 = mv.z ? 0.0f : fmaf(scale, ac[2], bb.z);
            float v3 = mv.w ? 0.0f : fmaf(scale, ac[3], bb.w);
            __nv_bfloat162 hp0 = __nv_bfloat162(__float2bfloat16(v0), __float2bfloat16(v1));
            __nv_bfloat162 hp1 = __nv_bfloat162(__float2bfloat16(v2), __float2bfloat16(v3));
            uint2 hv = make_uint2(*(uint32_t*)&hp0, *(uint32_t*)&hp1);
            *(uint2*)(Xh + xrow + gk) = hv;
        }
    }
}

// ---------------- softmax over last dim (row length 2048), in-place ----------------
__global__ __launch_bounds__(256)
void softmax_kernel(float* __restrict__ Y)
{
    float* p = Y + (size_t)blockIdx.x * SS;
    const int tid = threadIdx.x;

    float v[8];
    float mx = -1e30f;
#pragma unroll
    for (int i = 0; i < 8; i++) {
        v[i] = p[tid + i * 256];
        mx = fmaxf(mx, v[i]);
    }
    __shared__ float sh[8];
#pragma unroll
    for (int o = 16; o > 0; o >>= 1) mx = fmaxf(mx, __shfl_xor_sync(0xffffffffu, mx, o));
    if ((tid & 31) == 0) sh[tid >> 5] = mx;
    __syncthreads();
    float bm = sh[0];
#pragma unroll
    for (int i = 1; i < 8; i++) bm = fmaxf(bm, sh[i]);
    __syncthreads();

    float sum = 0.0f;
#pragma unroll
    for (int i = 0; i < 8; i++) {
        v[i] = expf(v[i] - bm);
        sum += v[i];
    }
#pragma unroll
    for (int o = 16; o > 0; o >>= 1) sum += __shfl_xor_sync(0xffffffffu, sum, o);
    if ((tid & 31) == 0) sh[tid >> 5] = sum;
    __syncthreads();
    float bs = 0.0f;
#pragma unroll
    for (int i = 0; i < 8; i++) bs += sh[i];
    const float inv = 1.0f / bs;
#pragma unroll
    for (int i = 0; i < 8; i++) p[tid + i * 256] = v[i] * inv;
}

// ---------------- launch ----------------
extern "C" void kernel_launch(void* const* d_in, const int* in_sizes, int n_in,
                              void* d_out, int out_size)
{
    const float*    q    = (const float*)d_in[0];
    const float*    k    = (const float*)d_in[1];
    const float*    v    = (const float*)d_in[2];
    const float*    bias = (const float*)d_in[3];
    const uint4*    mask = (const uint4*)d_in[4];
    const float*    w    = (const float*)d_in[5];
    const float*    Wq   = (const float*)d_in[6];
    const float*    bq   = (const float*)d_in[7];
    const float*    Wk   = (const float*)d_in[8];
    const float*    bk   = (const float*)d_in[9];
    const float*    Wv   = (const float*)d_in[10];
    const float*    bv   = (const float*)d_in[11];
    const float*    Wo   = (const float*)d_in[12];
    const float*    bo   = (const float*)d_in[13];
    float* out = (float*)d_out;

    float *qh, *kh, *vh, *Y, *O;
    __nv_bfloat16 *Xh, *whT;
    cudaGetSymbolAddress((void**)&qh,  g_qh);
    cudaGetSymbolAddress((void**)&kh,  g_kh);
    cudaGetSymbolAddress((void**)&vh,  g_vh);
    cudaGetSymbolAddress((void**)&Y,   g_Y);
    cudaGetSymbolAddress((void**)&O,   g_O);
    cudaGetSymbolAddress((void**)&Xh,  g_Xh);
    cudaGetSymbolAddress((void**)&whT, g_whT);

    cudaFuncSetAttribute(xw_mma_kernel, cudaFuncAttributeMaxDynamicSharedMemorySize, XW_SMEM);
    cudaFuncSetAttribute(scores_kernel, cudaFuncAttributeMaxDynamicSharedMemorySize, SC_SMEM);

    const size_t SSs = (size_t)SS * SS;

    // 0) w -> bf16 transposed
    {
        dim3 grid(SS / 32, SS / 32, BB);
        convw_kernel<<<grid, 256>>>(w, whT);
    }

    // 1) QKV projections
    {
        dim3 grid(HID / 128, (BB * SS) / 128, 1);
        gemm128<true, true><<<grid, 256>>>(q, Wq, bq, qh,
            BB * SS, HID, HID, HID, HID, HID, 1, 0, 0, 0, 0, 0, 0);
        gemm128<true, true><<<grid, 256>>>(k, Wk, bk, kh,
            BB * SS, HID, HID, HID, HID, HID, 1, 0, 0, 0, 0, 0, 0);
        gemm128<true, true><<<grid, 256>>>(v, Wv, bv, vh,
            BB * SS, HID, HID, HID, HID, HID, 1, 0, 0, 0, 0, 0, 0);
    }

    // 2) scores + bias + mask -> Xh bf16
    {
        dim3 grid(SS / 128, SS / 128, BB * NHH);
        scores_kernel<<<grid, 256, SC_SMEM>>>(qh, kh, bias, mask, Xh);
    }

    // 3) Y = Xh @ whT'  via mma.sync bf16
    {
        dim3 grid(SS / 128, (BB * NHH * SS) / 128, 1);
        xw_mma_kernel<<<grid, 256, XW_SMEM>>>(Xh, whT, Y);
    }

    // 4) softmax rows of Y in-place
    softmax_kernel<<<BB * NHH * SS, 256>>>(Y);

    // 5) O = P @ vh
    {
        dim3 grid(1, SS / 128, BB * NHH);
        gemm128<false, false><<<grid, 256>>>(Y, vh, nullptr, O,
            SS, DD, SS, SS, HID, HID,
            8,
            (size_t)NHH * SSs, SSs,
            (size_t)SS * HID, (size_t)DD,
            (size_t)SS * HID, (size_t)DD);
    }

    // 6) out = O @ Wo^T + bo
    {
        dim3 grid(HID / 128, (BB * SS) / 128, 1);
        gemm128<true, true><<<grid, 256>>>(O, Wo, bo, out,
            BB * SS, HID, HID, HID, HID, HID, 1, 0, 0, 0, 0, 0, 0);
    }
}

// round 12
// speedup vs baseline: 4.0494x; 1.2022x over previous
#include <cuda_runtime.h>
#include <cuda_bf16.h>
#include <cstdint>
#include <math.h>

// Problem dims
#define BB   2
#define SS   2048
#define HID  512
#define NHH  8
#define DD   64

// ---------------- scratch (static device globals; no allocation) ----------------
__device__ float g_qh[(size_t)BB * SS * HID];
__device__ float g_kh[(size_t)BB * SS * HID];
__device__ float g_vh[(size_t)BB * SS * HID];
__device__ __nv_bfloat16 g_Xh[(size_t)BB * NHH * SS * SS];   // bf16 masked scores; reused as Ph
__device__ __nv_bfloat16 g_Pl[(size_t)BB * NHH * SS * SS];   // lo residual of probs
__device__ __nv_bfloat16 g_whT[(size_t)BB * SS * SS];        // w^T bf16  [b][l][k]
__device__ __nv_bfloat16 g_vhTh[(size_t)BB * HID * SS];      // vh^T hi  [b][hd][s]
__device__ __nv_bfloat16 g_vhTl[(size_t)BB * HID * SS];      // vh^T lo
__device__ float g_Y [(size_t)BB * NHH * SS * SS];           // X@w logits
__device__ float g_O [(size_t)BB * SS * HID];

// ================= helpers =================
__device__ __forceinline__ uint32_t smem_u32(const void* p) {
    uint32_t a;
    asm("{ .reg .u64 t; cvta.to.shared.u64 t, %1; cvt.u32.u64 %0, t; }" : "=r"(a) : "l"(p));
    return a;
}
__device__ __forceinline__ uint32_t sw128(uint32_t o) { return o ^ ((o >> 3) & 0x70); }

__device__ __forceinline__ void ldsm4(uint32_t& r0, uint32_t& r1, uint32_t& r2, uint32_t& r3, uint32_t addr) {
    asm volatile("ldmatrix.sync.aligned.m8n8.x4.shared.b16 {%0,%1,%2,%3}, [%4];"
        : "=r"(r0), "=r"(r1), "=r"(r2), "=r"(r3) : "r"(addr));
}
__device__ __forceinline__ void mma16816(float* d, const uint32_t* a, const uint32_t* b) {
    asm volatile("mma.sync.aligned.m16n8k16.row.col.f32.bf16.bf16.f32 "
        "{%0,%1,%2,%3}, {%4,%5,%6,%7}, {%8,%9}, {%0,%1,%2,%3};"
        : "+f"(d[0]), "+f"(d[1]), "+f"(d[2]), "+f"(d[3])
        : "r"(a[0]), "r"(a[1]), "r"(a[2]), "r"(a[3]), "r"(b[0]), "r"(b[1]));
}
__device__ __forceinline__ void cpa16(uint32_t dst, const void* src) {
    asm volatile("cp.async.cg.shared.global [%0], [%1], 16;" :: "r"(dst), "l"(src));
}

// ================= x@w GEMM via mma.sync bf16 =================
// Y = Xh @ whT'  (plain bf16 GEMM, K=2048), fp32 accum.
// CTA 128x128, 8 warps (4m x 2n), warp tile 32x64, K-chunk 64.
#define XW_STAGE 32768
#define XW_SMEM  (3 * XW_STAGE)
#define XW_NCHUNK 32

__device__ __forceinline__ void xw_load(
    uint32_t sbase, int slot, int chunk,
    const __nv_bfloat16* __restrict__ Xh,
    const __nv_bfloat16* __restrict__ whb,
    int m0, int n0, int tid)
{
    const int kk = chunk * 64;
    const uint32_t base = sbase + (uint32_t)slot * XW_STAGE;
    const int row  = tid >> 1;
    const int half = tid & 1;
    const __nv_bfloat16* arow = Xh  + (size_t)(m0 + row) * SS + kk + half * 32;
    const __nv_bfloat16* brow = whb + (size_t)(n0 + row) * SS + kk + half * 32;
    const uint32_t roff = (uint32_t)row * 128 + (uint32_t)half * 64;
#pragma unroll
    for (int c = 0; c < 4; c++) {
        uint32_t s = sw128(roff + c * 16);
        cpa16(base +         s, arow + c * 8);
        cpa16(base + 16384 + s, brow + c * 8);
    }
}

__device__ __forceinline__ void xw_compute(uint32_t stg, int wm, int wn, int lane,
                                           float acc[2][8][4])
{
    const uint32_t aB = stg, bB = stg + 16384;
    const uint32_t a_base = (uint32_t)(wm * 32 + (lane & 15)) * 128 + (uint32_t)((lane >> 4) * 16);
    const uint32_t b_base = (uint32_t)(wn * 64 + (lane & 7) + ((lane >> 4) << 3)) * 128
                          + (uint32_t)(((lane >> 3) & 1) * 16);
#pragma unroll
    for (int ks = 0; ks < 4; ks++) {
        const uint32_t k0b = (uint32_t)ks * 32;
        uint32_t a[2][4], b[8][2];
#pragma unroll
        for (int mb = 0; mb < 2; mb++) {
            uint32_t s = sw128(a_base + (uint32_t)mb * 2048 + k0b);
            ldsm4(a[mb][0], a[mb][1], a[mb][2], a[mb][3], aB + s);
        }
#pragma unroll
        for (int nb2 = 0; nb2 < 4; nb2++) {
            uint32_t s = sw128(b_base + (uint32_t)nb2 * 2048 + k0b);
            uint32_t r0, r1, r2, r3;
            ldsm4(r0, r1, r2, r3, bB + s);
            b[2 * nb2][0] = r0; b[2 * nb2][1] = r1;
            b[2 * nb2 + 1][0] = r2; b[2 * nb2 + 1][1] = r3;
        }
#pragma unroll
        for (int mb = 0; mb < 2; mb++)
#pragma unroll
            for (int nb = 0; nb < 8; nb++)
                mma16816(acc[mb][nb], a[mb], b[nb]);
    }
}

__global__ __launch_bounds__(256, 2)
void xw_mma_kernel(const __nv_bfloat16* __restrict__ Xh,
                   const __nv_bfloat16* __restrict__ whT, float* __restrict__ Y)
{
    extern __shared__ char smem[];
    const uint32_t sbase = smem_u32(smem);
    const int tid  = threadIdx.x;
    const int wid  = tid >> 5;
    const int lane = tid & 31;
    const int wm   = wid & 3;
    const int wn   = wid >> 2;
    const int n0   = blockIdx.x * 128;
    const int m0   = blockIdx.y * 128;
    const int batch = m0 >> 14;
    const __nv_bfloat16* whb = whT + (size_t)batch * SS * SS;

    float acc[2][8][4];
#pragma unroll
    for (int i = 0; i < 2; i++)
#pragma unroll
        for (int j = 0; j < 8; j++)
#pragma unroll
            for (int r = 0; r < 4; r++) acc[i][j][r] = 0.0f;

#pragma unroll
    for (int j = 0; j < 3; j++) {
        xw_load(sbase, j, j, Xh, whb, m0, n0, tid);
        asm volatile("cp.async.commit_group;" ::: "memory");
    }

    for (int i = 0; i < XW_NCHUNK; i++) {
        const int s = i % 3;
        asm volatile("cp.async.wait_group 2;" ::: "memory");
        __syncthreads();
        xw_compute(sbase + (uint32_t)s * XW_STAGE, wm, wn, lane, acc);
        __syncthreads();
        if (i + 3 < XW_NCHUNK)
            xw_load(sbase, s, i + 3, Xh, whb, m0, n0, tid);
        asm volatile("cp.async.commit_group;" ::: "memory");
    }

    const int r  = lane >> 2;
    const int c2 = (lane & 3) * 2;
#pragma unroll
    for (int mb = 0; mb < 2; mb++) {
        const int row = m0 + wm * 32 + mb * 16 + r;
#pragma unroll
        for (int nb = 0; nb < 8; nb++) {
            const int col = n0 + wn * 64 + nb * 8 + c2;
            float2 v0 = make_float2(acc[mb][nb][0], acc[mb][nb][1]);
            float2 v1 = make_float2(acc[mb][nb][2], acc[mb][nb][3]);
            *(float2*)(Y + (size_t)row * SS + col)       = v0;
            *(float2*)(Y + (size_t)(row + 8) * SS + col) = v1;
        }
    }
}

// ================= PV GEMM via mma.sync bf16, 3-term K-concat =================
// O[:,h*64:+64] = Ph@Vh + Pl@Vh + Ph@Vl  (K = 3*2048 concat, fp32 accum)
// CTA 128(M) x 64(N), 8 warps (4m x 2n), warp tile 32x32, K-chunk 64.
// Stage: A 16KB + B 8KB = 24KB; 3 stages = 72KB.
#define PV_STAGE 24576
#define PV_SMEM  (3 * PV_STAGE)
#define PV_NCHUNK 96

__device__ __forceinline__ void pv_load(
    uint32_t sbase, int slot, int chunk,
    const __nv_bfloat16* __restrict__ Ph, const __nv_bfloat16* __restrict__ Pl,
    const __nv_bfloat16* __restrict__ Vh, const __nv_bfloat16* __restrict__ Vl,
    size_t arow0, size_t brow0, int tid)
{
    const int seg = chunk >> 5;               // 0: Ph*Vh, 1: Pl*Vh, 2: Ph*Vl
    const int kk  = (chunk & 31) * 64;
    const uint32_t base = sbase + (uint32_t)slot * PV_STAGE;
    {
        const __nv_bfloat16* As = (seg == 1) ? Pl : Ph;
        const int row  = tid >> 1;
        const int half = tid & 1;
        const __nv_bfloat16* arow = As + (arow0 + row) * SS + kk + half * 32;
        const uint32_t roff = (uint32_t)row * 128 + (uint32_t)half * 64;
#pragma unroll
        for (int c = 0; c < 4; c++)
            cpa16(base + sw128(roff + c * 16), arow + c * 8);
    }
    if (tid < 128) {
        const __nv_bfloat16* Bs = (seg == 2) ? Vl : Vh;
        const int row  = tid >> 1;            // 0..63
        const int half = tid & 1;
        const __nv_bfloat16* brow = Bs + (brow0 + row) * SS + kk + half * 32;
        const uint32_t roff = (uint32_t)row * 128 + (uint32_t)half * 64;
#pragma unroll
        for (int c = 0; c < 4; c++)
            cpa16(base + 16384 + sw128(roff + c * 16), brow + c * 8);
    }
}

__global__ __launch_bounds__(256, 2)
void pv_mma_kernel(const __nv_bfloat16* __restrict__ Ph, const __nv_bfloat16* __restrict__ Pl,
                   const __nv_bfloat16* __restrict__ vhTh, const __nv_bfloat16* __restrict__ vhTl,
                   float* __restrict__ O)
{
    extern __shared__ char smem[];
    const uint32_t sbase = smem_u32(smem);
    const int tid  = threadIdx.x;
    const int wid  = tid >> 5;
    const int lane = tid & 31;
    const int wm   = wid & 3;
    const int wn   = wid >> 2;
    const int bh   = blockIdx.y;              // 0..15
    const int b    = bh >> 3;
    const int h    = bh & 7;
    const int m0   = blockIdx.x * 128;        // seq offset within (b,h)
    const size_t arow0 = (size_t)bh * SS + m0;
    const size_t brow0 = (size_t)b * HID + h * DD;

    float acc[2][4][4];
#pragma unroll
    for (int i = 0; i < 2; i++)
#pragma unroll
        for (int j = 0; j < 4; j++)
#pragma unroll
            for (int r = 0; r < 4; r++) acc[i][j][r] = 0.0f;

#pragma unroll
    for (int j = 0; j < 3; j++) {
        pv_load(sbase, j, j, Ph, Pl, vhTh, vhTl, arow0, brow0, tid);
        asm volatile("cp.async.commit_group;" ::: "memory");
    }

    for (int i = 0; i < PV_NCHUNK; i++) {
        const int s = i % 3;
        asm volatile("cp.async.wait_group 2;" ::: "memory");
        __syncthreads();
        {
            const uint32_t stg = sbase + (uint32_t)s * PV_STAGE;
            const uint32_t aB = stg, bB = stg + 16384;
            const uint32_t a_base = (uint32_t)(wm * 32 + (lane & 15)) * 128 + (uint32_t)((lane >> 4) * 16);
            const uint32_t b_base = (uint32_t)(wn * 32 + (lane & 7) + ((lane >> 4) << 3)) * 128
                                  + (uint32_t)(((lane >> 3) & 1) * 16);
#pragma unroll
            for (int ks = 0; ks < 4; ks++) {
                const uint32_t k0b = (uint32_t)ks * 32;
                uint32_t a[2][4], bfr[4][2];
#pragma unroll
                for (int mb = 0; mb < 2; mb++) {
                    uint32_t sw = sw128(a_base + (uint32_t)mb * 2048 + k0b);
                    ldsm4(a[mb][0], a[mb][1], a[mb][2], a[mb][3], aB + sw);
                }
#pragma unroll
                for (int nb2 = 0; nb2 < 2; nb2++) {
                    uint32_t sw = sw128(b_base + (uint32_t)nb2 * 2048 + k0b);
                    uint32_t r0, r1, r2, r3;
                    ldsm4(r0, r1, r2, r3, bB + sw);
                    bfr[2 * nb2][0] = r0; bfr[2 * nb2][1] = r1;
                    bfr[2 * nb2 + 1][0] = r2; bfr[2 * nb2 + 1][1] = r3;
                }
#pragma unroll
                for (int mb = 0; mb < 2; mb++)
#pragma unroll
                    for (int nb = 0; nb < 4; nb++)
                        mma16816(acc[mb][nb], a[mb], bfr[nb]);
            }
        }
        __syncthreads();
        if (i + 3 < PV_NCHUNK)
            pv_load(sbase, s, i + 3, Ph, Pl, vhTh, vhTl, arow0, brow0, tid);
        asm volatile("cp.async.commit_group;" ::: "memory");
    }

    // epilogue: O[(b*SS + s)*HID + h*64 + col]
    const int r  = lane >> 2;
    const int c2 = (lane & 3) * 2;
#pragma unroll
    for (int mb = 0; mb < 2; mb++) {
        const int srow = m0 + wm * 32 + mb * 16 + r;
#pragma unroll
        for (int nb = 0; nb < 4; nb++) {
            const int col = wn * 32 + nb * 8 + c2;
            float* o0 = O + ((size_t)b * SS + srow) * HID + h * DD + col;
            *(float2*)o0                      = make_float2(acc[mb][nb][0], acc[mb][nb][1]);
            *(float2*)(o0 + (size_t)8 * HID)  = make_float2(acc[mb][nb][2], acc[mb][nb][3]);
        }
    }
}

// ================= w -> bf16 transpose =================
__global__ __launch_bounds__(256)
void convw_kernel(const float* __restrict__ w, __nv_bfloat16* __restrict__ whT)
{
    __shared__ float t[32][33];
    const int b  = blockIdx.z;
    const int k0 = blockIdx.y * 32;
    const int l0 = blockIdx.x * 32;
    const float* wb = w + (size_t)b * SS * SS;
    const int tx = threadIdx.x & 31;
    const int ty = threadIdx.x >> 5;
#pragma unroll
    for (int i = 0; i < 4; i++)
        t[ty + 8 * i][tx] = wb[(size_t)(k0 + ty + 8 * i) * SS + l0 + tx];
    __syncthreads();
#pragma unroll
    for (int i = 0; i < 4; i++) {
        float v = t[tx][ty + 8 * i];
        size_t idx = (size_t)b * SS * SS + (size_t)(l0 + ty + 8 * i) * SS + (k0 + tx);
        whT[idx] = __float2bfloat16(v);
    }
}

// ================= vh -> bf16 hi/lo transpose: [B,S,HID] -> [B,HID,S] =================
__global__ __launch_bounds__(256)
void convv_kernel(const float* __restrict__ vh,
                  __nv_bfloat16* __restrict__ vhTh, __nv_bfloat16* __restrict__ vhTl)
{
    __shared__ float t[32][33];
    const int b  = blockIdx.z;
    const int s0 = blockIdx.y * 32;
    const int d0 = blockIdx.x * 32;
    const int tx = threadIdx.x & 31;
    const int ty = threadIdx.x >> 5;
#pragma unroll
    for (int i = 0; i < 4; i++)
        t[ty + 8 * i][tx] = vh[((size_t)b * SS + s0 + ty + 8 * i) * HID + d0 + tx];
    __syncthreads();
#pragma unroll
    for (int i = 0; i < 4; i++) {
        float v = t[tx][ty + 8 * i];              // vh[b][s0+tx][d0+ty+8i]
        size_t idx = ((size_t)b * HID + d0 + ty + 8 * i) * SS + s0 + tx;
        __nv_bfloat16 hv = __float2bfloat16(v);
        vhTh[idx] = hv;
        vhTl[idx] = __float2bfloat16(v - __bfloat162float(hv));
    }
}

// ---------------- fp32 GEMM body (NT + bias), 128x128 tile ----------------
__device__ __forceinline__ void gemm_nt_body(
    const float* __restrict__ A, const float* __restrict__ Bm,
    const float* __restrict__ bias, float* __restrict__ C,
    int N, int K, int lda, int ldb, int ldc, int m0, int n0)
{
    __shared__ float As[16][132];
    __shared__ float Bs[16][132];

    const int tid = threadIdx.x;
    const int tx  = tid & 15;
    const int ty  = tid >> 4;

    float acc[8][8];
#pragma unroll
    for (int i = 0; i < 8; i++)
#pragma unroll
        for (int j = 0; j < 8; j++) acc[i][j] = 0.0f;

    for (int k0 = 0; k0 < K; k0 += 16) {
        const int r  = tid >> 2;
        const int kq = (tid & 3) * 4;
#pragma unroll
        for (int half = 0; half < 2; half++) {
            const int row = r + half * 64;
            float4 v = *(const float4*)(A + (size_t)(m0 + row) * lda + k0 + kq);
            As[kq + 0][row] = v.x; As[kq + 1][row] = v.y;
            As[kq + 2][row] = v.z; As[kq + 3][row] = v.w;
            float4 u = *(const float4*)(Bm + (size_t)(n0 + row) * ldb + k0 + kq);
            Bs[kq + 0][row] = u.x; Bs[kq + 1][row] = u.y;
            Bs[kq + 2][row] = u.z; Bs[kq + 3][row] = u.w;
        }
        __syncthreads();

#pragma unroll
        for (int kk = 0; kk < 16; kk++) {
            float a[8], b[8];
            *(float4*)&a[0] = *(const float4*)&As[kk][ty * 4];
            *(float4*)&a[4] = *(const float4*)&As[kk][64 + ty * 4];
            *(float4*)&b[0] = *(const float4*)&Bs[kk][tx * 4];
            *(float4*)&b[4] = *(const float4*)&Bs[kk][64 + tx * 4];
#pragma unroll
            for (int i = 0; i < 8; i++)
#pragma unroll
                for (int j = 0; j < 8; j++)
                    acc[i][j] = fmaf(a[i], b[j], acc[i][j]);
        }
        __syncthreads();
    }

#pragma unroll
    for (int i = 0; i < 8; i++) {
        const int lm = (i < 4) ? (ty * 4 + i) : (64 + ty * 4 + i - 4);
#pragma unroll
        for (int j = 0; j < 8; j++) {
            const int ln = (j < 4) ? (tx * 4 + j) : (64 + tx * 4 + j - 4);
            C[(size_t)(m0 + lm) * ldc + n0 + ln] = acc[i][j] + bias[n0 + ln];
        }
    }
}

// fused QKV projection: z picks (q,Wq,bq,qh) / (k,...) / (v,...)
__global__ __launch_bounds__(256)
void qkv_kernel(const float* __restrict__ q, const float* __restrict__ k, const float* __restrict__ v,
                const float* __restrict__ Wq, const float* __restrict__ Wk, const float* __restrict__ Wv,
                const float* __restrict__ bq, const float* __restrict__ bk, const float* __restrict__ bv,
                float* __restrict__ qh, float* __restrict__ kh, float* __restrict__ vh)
{
    const int z = blockIdx.z;
    const float* A  = (z == 0) ? q  : (z == 1) ? k  : v;
    const float* W  = (z == 0) ? Wq : (z == 1) ? Wk : Wv;
    const float* bi = (z == 0) ? bq : (z == 1) ? bk : bv;
    float*       C  = (z == 0) ? qh : (z == 1) ? kh : vh;
    gemm_nt_body(A, W, bi, C, HID, HID, HID, HID, HID,
                 blockIdx.y * 128, blockIdx.x * 128);
}

// output projection
__global__ __launch_bounds__(256)
void outproj_kernel(const float* __restrict__ O, const float* __restrict__ Wo,
                    const float* __restrict__ bo, float* __restrict__ out)
{
    gemm_nt_body(O, Wo, bo, out, HID, HID, HID, HID, HID,
                 blockIdx.y * 128, blockIdx.x * 128);
}

// ---------------- scores: 128x128 tile, K-major smem, 8x8 microtile ----------------
#define SC_SMEM (2 * 64 * 132 * 4)

__global__ __launch_bounds__(256)
void scores_kernel(const float* __restrict__ qhp, const float* __restrict__ khp,
                   const float* __restrict__ attn_bias, const uint4* __restrict__ mask,
                   __nv_bfloat16* __restrict__ Xh)
{
    extern __shared__ char smemraw[];
    float (*qs)[132] = (float (*)[132])smemraw;
    float (*ks)[132] = (float (*)[132])(smemraw + 64 * 132 * 4);

    const int bh = blockIdx.z;
    const int b  = bh >> 3;
    const int h  = bh & 7;
    const int q0 = blockIdx.y * 128;
    const int k0 = blockIdx.x * 128;

    const int tid = threadIdx.x;
    {
        const int m  = tid >> 1;
        const int d0 = (tid & 1) * 32;
        const float* qrow = qhp + (size_t)(b * SS + q0 + m) * HID + h * DD + d0;
        const float* krow = khp + (size_t)(b * SS + k0 + m) * HID + h * DD + d0;
#pragma unroll
        for (int c = 0; c < 8; c++) {
            float4 v = *(const float4*)(qrow + c * 4);
            qs[d0 + c * 4 + 0][m] = v.x; qs[d0 + c * 4 + 1][m] = v.y;
            qs[d0 + c * 4 + 2][m] = v.z; qs[d0 + c * 4 + 3][m] = v.w;
            v = *(const float4*)(krow + c * 4);
            ks[d0 + c * 4 + 0][m] = v.x; ks[d0 + c * 4 + 1][m] = v.y;
            ks[d0 + c * 4 + 2][m] = v.z; ks[d0 + c * 4 + 3][m] = v.w;
        }
    }
    __syncthreads();

    const int tx = tid & 15;
    const int ty = tid >> 4;
    float acc[8][8];
#pragma unroll
    for (int i = 0; i < 8; i++)
#pragma unroll
        for (int j = 0; j < 8; j++) acc[i][j] = 0.0f;

#pragma unroll 4
    for (int d = 0; d < 64; d++) {
        float a[8], bv[8];
        *(float4*)&a[0]  = *(const float4*)&qs[d][ty * 4];
        *(float4*)&a[4]  = *(const float4*)&qs[d][64 + ty * 4];
        *(float4*)&bv[0] = *(const float4*)&ks[d][tx * 4];
        *(float4*)&bv[4] = *(const float4*)&ks[d][64 + tx * 4];
#pragma unroll
        for (int i = 0; i < 8; i++)
#pragma unroll
            for (int j = 0; j < 8; j++)
                acc[i][j] = fmaf(a[i], bv[j], acc[i][j]);
    }

    const float scale = 0.125f;
#pragma unroll
    for (int i = 0; i < 8; i++) {
        const int gq = q0 + ((i < 4) ? (ty * 4 + i) : (64 + ty * 4 + i - 4));
        const size_t mrow = ((size_t)b * SS + gq) * SS;
        const size_t xrow = ((size_t)bh * SS + gq) * SS;
#pragma unroll
        for (int jh = 0; jh < 2; jh++) {
            const int gk = k0 + jh * 64 + tx * 4;
            uint4  mv = mask[(mrow + gk) >> 2];
            float4 bb = *(const float4*)(attn_bias + xrow + gk);
            const float* ac = &acc[i][jh * 4];
            float v0 = mv.x ? 0.0f : fmaf(scale, ac[0], bb.x);
            float v1 = mv.y ? 0.0f : fmaf(scale, ac[1], bb.y);
            float v2 = mv.z ? 0.0f : fmaf(scale, ac[2], bb.z);
            float v3 = mv.w ? 0.0f : fmaf(scale, ac[3], bb.w);
            __nv_bfloat162 hp0 = __nv_bfloat162(__float2bfloat16(v0), __float2bfloat16(v1));
            __nv_bfloat162 hp1 = __nv_bfloat162(__float2bfloat16(v2), __float2bfloat16(v3));
            uint2 hv = make_uint2(*(uint32_t*)&hp0, *(uint32_t*)&hp1);
            *(uint2*)(Xh + xrow + gk) = hv;
        }
    }
}

// ---------------- softmax: read logits fp32, write probs as bf16 hi/lo ----------------
__global__ __launch_bounds__(256)
void softmax_kernel(const float* __restrict__ Y,
                    __nv_bfloat16* __restrict__ Ph, __nv_bfloat16* __restrict__ Pl)
{
    const float* p = Y + (size_t)blockIdx.x * SS;
    const int tid = threadIdx.x;

    float v[8];
    float mx = -1e30f;
#pragma unroll
    for (int i = 0; i < 8; i++) {
        v[i] = p[tid + i * 256];
        mx = fmaxf(mx, v[i]);
    }
    __shared__ float sh[8];
#pragma unroll
    for (int o = 16; o > 0; o >>= 1) mx = fmaxf(mx, __shfl_xor_sync(0xffffffffu, mx, o));
    if ((tid & 31) == 0) sh[tid >> 5] = mx;
    __syncthreads();
    float bm = sh[0];
#pragma unroll
    for (int i = 1; i < 8; i++) bm = fmaxf(bm, sh[i]);
    __syncthreads();

    float sum = 0.0f;
#pragma unroll
    for (int i = 0; i < 8; i++) {
        v[i] = expf(v[i] - bm);
        sum += v[i];
    }
#pragma unroll
    for (int o = 16; o > 0; o >>= 1) sum += __shfl_xor_sync(0xffffffffu, sum, o);
    if ((tid & 31) == 0) sh[tid >> 5] = sum;
    __syncthreads();
    float bs = 0.0f;
#pragma unroll
    for (int i = 0; i < 8; i++) bs += sh[i];
    const float inv = 1.0f / bs;

    __nv_bfloat16* ph = Ph + (size_t)blockIdx.x * SS;
    __nv_bfloat16* pl = Pl + (size_t)blockIdx.x * SS;
#pragma unroll
    for (int i = 0; i < 8; i++) {
        float pv = v[i] * inv;
        __nv_bfloat16 hv = __float2bfloat16(pv);
        ph[tid + i * 256] = hv;
        pl[tid + i * 256] = __float2bfloat16(pv - __bfloat162float(hv));
    }
}

// ---------------- launch ----------------
extern "C" void kernel_launch(void* const* d_in, const int* in_sizes, int n_in,
                              void* d_out, int out_size)
{
    const float*    q    = (const float*)d_in[0];
    const float*    k    = (const float*)d_in[1];
    const float*    v    = (const float*)d_in[2];
    const float*    bias = (const float*)d_in[3];
    const uint4*    mask = (const uint4*)d_in[4];
    const float*    w    = (const float*)d_in[5];
    const float*    Wq   = (const float*)d_in[6];
    const float*    bq   = (const float*)d_in[7];
    const float*    Wk   = (const float*)d_in[8];
    const float*    bk   = (const float*)d_in[9];
    const float*    Wv   = (const float*)d_in[10];
    const float*    bv   = (const float*)d_in[11];
    const float*    Wo   = (const float*)d_in[12];
    const float*    bo   = (const float*)d_in[13];
    float* out = (float*)d_out;

    float *qh, *kh, *vh, *Y, *O;
    __nv_bfloat16 *Xh, *Pl, *whT, *vhTh, *vhTl;
    cudaGetSymbolAddress((void**)&qh,   g_qh);
    cudaGetSymbolAddress((void**)&kh,   g_kh);
    cudaGetSymbolAddress((void**)&vh,   g_vh);
    cudaGetSymbolAddress((void**)&Y,    g_Y);
    cudaGetSymbolAddress((void**)&O,    g_O);
    cudaGetSymbolAddress((void**)&Xh,   g_Xh);
    cudaGetSymbolAddress((void**)&Pl,   g_Pl);
    cudaGetSymbolAddress((void**)&whT,  g_whT);
    cudaGetSymbolAddress((void**)&vhTh, g_vhTh);
    cudaGetSymbolAddress((void**)&vhTl, g_vhTl);

    cudaFuncSetAttribute(xw_mma_kernel, cudaFuncAttributeMaxDynamicSharedMemorySize, XW_SMEM);
    cudaFuncSetAttribute(pv_mma_kernel, cudaFuncAttributeMaxDynamicSharedMemorySize, PV_SMEM);
    cudaFuncSetAttribute(scores_kernel, cudaFuncAttributeMaxDynamicSharedMemorySize, SC_SMEM);

    // 0) w -> bf16 transposed
    {
        dim3 grid(SS / 32, SS / 32, BB);
        convw_kernel<<<grid, 256>>>(w, whT);
    }

    // 1) fused QKV projections
    {
        dim3 grid(HID / 128, (BB * SS) / 128, 3);
        qkv_kernel<<<grid, 256>>>(q, k, v, Wq, Wk, Wv, bq, bk, bv, qh, kh, vh);
    }

    // 1b) vh -> bf16 hi/lo transpose
    {
        dim3 grid(HID / 32, SS / 32, BB);
        convv_kernel<<<grid, 256>>>(vh, vhTh, vhTl);
    }

    // 2) scores + bias + mask -> Xh bf16
    {
        dim3 grid(SS / 128, SS / 128, BB * NHH);
        scores_kernel<<<grid, 256, SC_SMEM>>>(qh, kh, bias, mask, Xh);
    }

    // 3) Y = Xh @ whT' via mma.sync bf16
    {
        dim3 grid(SS / 128, (BB * NHH * SS) / 128, 1);
        xw_mma_kernel<<<grid, 256, XW_SMEM>>>(Xh, whT, Y);
    }

    // 4) softmax -> Ph (reuses Xh buffer) + Pl bf16
    softmax_kernel<<<BB * NHH * SS, 256>>>(Y, Xh, Pl);

    // 5) O = P @ vh via mma.sync bf16 3-term
    {
        dim3 grid(SS / 128, BB * NHH, 1);
        pv_mma_kernel<<<grid, 256, PV_SMEM>>>(Xh, Pl, vhTh, vhTl, O);
    }

    // 6) out = O @ Wo^T + bo
    {
        dim3 grid(HID / 128, (BB * SS) / 128, 1);
        outproj_kernel<<<grid, 256>>>(O, Wo, bo, out);
    }
}

// round 16
// speedup vs baseline: 4.1403x; 1.0224x over previous
#include <cuda_runtime.h>
#include <cuda_bf16.h>
#include <cstdint>
#include <math.h>

// Problem dims
#define BB   2
#define SS   2048
#define HID  512
#define NHH  8
#define DD   64

// ---------------- scratch (static device globals; no allocation) ----------------
__device__ float g_qh[(size_t)BB * SS * HID];
__device__ float g_kh[(size_t)BB * SS * HID];
__device__ float g_vh[(size_t)BB * SS * HID];
__device__ __nv_bfloat16 g_Xh[(size_t)BB * NHH * SS * SS];   // bf16 masked scores
__device__ __nv_bfloat16 g_whT[(size_t)BB * SS * SS];        // w^T bf16  [b][l][k]
__device__ __nv_bfloat16 g_E[(size_t)2 * BB * NHH * SS * SS];// Eh | El  (exp of logits, hi/lo)
__device__ float g_rsum[(size_t)BB * NHH * SS];              // row sums of exp
__device__ __nv_bfloat16 g_vhTh[(size_t)BB * HID * SS];      // vh^T hi  [b][hd][s]
__device__ __nv_bfloat16 g_vhTl[(size_t)BB * HID * SS];      // vh^T lo
__device__ float g_O [(size_t)BB * SS * HID];

// ================= helpers =================
__device__ __forceinline__ uint32_t smem_u32(const void* p) {
    uint32_t a;
    asm("{ .reg .u64 t; cvta.to.shared.u64 t, %1; cvt.u32.u64 %0, t; }" : "=r"(a) : "l"(p));
    return a;
}
__device__ __forceinline__ uint32_t sw128(uint32_t o) { return o ^ ((o >> 3) & 0x70); }

__device__ __forceinline__ void ldsm4(uint32_t& r0, uint32_t& r1, uint32_t& r2, uint32_t& r3, uint32_t addr) {
    asm volatile("ldmatrix.sync.aligned.m8n8.x4.shared.b16 {%0,%1,%2,%3}, [%4];"
        : "=r"(r0), "=r"(r1), "=r"(r2), "=r"(r3) : "r"(addr));
}
__device__ __forceinline__ void mma16816(float* d, const uint32_t* a, const uint32_t* b) {
    asm volatile("mma.sync.aligned.m16n8k16.row.col.f32.bf16.bf16.f32 "
        "{%0,%1,%2,%3}, {%4,%5,%6,%7}, {%8,%9}, {%0,%1,%2,%3};"
        : "+f"(d[0]), "+f"(d[1]), "+f"(d[2]), "+f"(d[3])
        : "r"(a[0]), "r"(a[1]), "r"(a[2]), "r"(a[3]), "r"(b[0]), "r"(b[1]));
}
__device__ __forceinline__ void cpa16(uint32_t dst, const void* src) {
    asm volatile("cp.async.cg.shared.global [%0], [%1], 16;" :: "r"(dst), "l"(src));
}

// ================= zero rowsum buffer =================
__global__ void zero_kernel(float* __restrict__ p, int n)
{
    int i = blockIdx.x * blockDim.x + threadIdx.x;
    if (i < n) p[i] = 0.0f;
}

// ================= x@w GEMM via mma.sync bf16, fused exp + rowsum =================
// E = exp(Xh @ whT') hi/lo bf16; rsum[row] += sum of exp.  (logits tiny -> no max pass)
// CTA 128x128, 8 warps (4m x 2n), warp tile 32x64, K-chunk 64.
#define XW_STAGE 32768
#define XW_SMEM  (3 * XW_STAGE)
#define XW_NCHUNK 32

__device__ __forceinline__ void xw_load(
    uint32_t sbase, int slot, int chunk,
    const __nv_bfloat16* __restrict__ Xh,
    const __nv_bfloat16* __restrict__ whb,
    int m0, int n0, int tid)
{
    const int kk = chunk * 64;
    const uint32_t base = sbase + (uint32_t)slot * XW_STAGE;
    const int row  = tid >> 1;
    const int half = tid & 1;
    const __nv_bfloat16* arow = Xh  + (size_t)(m0 + row) * SS + kk + half * 32;
    const __nv_bfloat16* brow = whb + (size_t)(n0 + row) * SS + kk + half * 32;
    const uint32_t roff = (uint32_t)row * 128 + (uint32_t)half * 64;
#pragma unroll
    for (int c = 0; c < 4; c++) {
        uint32_t s = sw128(roff + c * 16);
        cpa16(base +         s, arow + c * 8);
        cpa16(base + 16384 + s, brow + c * 8);
    }
}

__device__ __forceinline__ void xw_compute(uint32_t stg, int wm, int wn, int lane,
                                           float acc[2][8][4])
{
    const uint32_t aB = stg, bB = stg + 16384;
    const uint32_t a_base = (uint32_t)(wm * 32 + (lane & 15)) * 128 + (uint32_t)((lane >> 4) * 16);
    const uint32_t b_base = (uint32_t)(wn * 64 + (lane & 7) + ((lane >> 4) << 3)) * 128
                          + (uint32_t)(((lane >> 3) & 1) * 16);
#pragma unroll
    for (int ks = 0; ks < 4; ks++) {
        const uint32_t k0b = (uint32_t)ks * 32;
        uint32_t a[2][4], b[8][2];
#pragma unroll
        for (int mb = 0; mb < 2; mb++) {
            uint32_t s = sw128(a_base + (uint32_t)mb * 2048 + k0b);
            ldsm4(a[mb][0], a[mb][1], a[mb][2], a[mb][3], aB + s);
        }
#pragma unroll
        for (int nb2 = 0; nb2 < 4; nb2++) {
            uint32_t s = sw128(b_base + (uint32_t)nb2 * 2048 + k0b);
            uint32_t r0, r1, r2, r3;
            ldsm4(r0, r1, r2, r3, bB + s);
            b[2 * nb2][0] = r0; b[2 * nb2][1] = r1;
            b[2 * nb2 + 1][0] = r2; b[2 * nb2 + 1][1] = r3;
        }
#pragma unroll
        for (int mb = 0; mb < 2; mb++)
#pragma unroll
            for (int nb = 0; nb < 8; nb++)
                mma16816(acc[mb][nb], a[mb], b[nb]);
    }
}

__global__ __launch_bounds__(256, 2)
void xw_mma_kernel(const __nv_bfloat16* __restrict__ Xh,
                   const __nv_bfloat16* __restrict__ whT,
                   __nv_bfloat16* __restrict__ Eh, __nv_bfloat16* __restrict__ El,
                   float* __restrict__ rsum)
{
    extern __shared__ char smem[];
    const uint32_t sbase = smem_u32(smem);
    const int tid  = threadIdx.x;
    const int wid  = tid >> 5;
    const int lane = tid & 31;
    const int wm   = wid & 3;
    const int wn   = wid >> 2;
    const int n0   = blockIdx.x * 128;
    const int m0   = blockIdx.y * 128;
    const int batch = m0 >> 14;
    const __nv_bfloat16* whb = whT + (size_t)batch * SS * SS;

    float acc[2][8][4];
#pragma unroll
    for (int i = 0; i < 2; i++)
#pragma unroll
        for (int j = 0; j < 8; j++)
#pragma unroll
            for (int r = 0; r < 4; r++) acc[i][j][r] = 0.0f;

#pragma unroll
    for (int j = 0; j < 3; j++) {
        xw_load(sbase, j, j, Xh, whb, m0, n0, tid);
        asm volatile("cp.async.commit_group;" ::: "memory");
    }

    for (int i = 0; i < XW_NCHUNK; i++) {
        const int s = i % 3;
        asm volatile("cp.async.wait_group 2;" ::: "memory");
        __syncthreads();
        xw_compute(sbase + (uint32_t)s * XW_STAGE, wm, wn, lane, acc);
        __syncthreads();
        if (i + 3 < XW_NCHUNK)
            xw_load(sbase, s, i + 3, Xh, whb, m0, n0, tid);
        asm volatile("cp.async.commit_group;" ::: "memory");
    }

    // epilogue: e = exp(acc); write bf16 hi/lo; accumulate row sums
    const int r  = lane >> 2;
    const int c2 = (lane & 3) * 2;
#pragma unroll
    for (int mb = 0; mb < 2; mb++) {
        const int row = m0 + wm * 32 + mb * 16 + r;
        float rsA = 0.0f, rsB = 0.0f;
#pragma unroll
        for (int nb = 0; nb < 8; nb++) {
            const int col = n0 + wn * 64 + nb * 8 + c2;
            float e0 = expf(acc[mb][nb][0]);
            float e1 = expf(acc[mb][nb][1]);
            float e2 = expf(acc[mb][nb][2]);
            float e3 = expf(acc[mb][nb][3]);
            rsA += e0 + e1;
            rsB += e2 + e3;
            __nv_bfloat16 h0 = __float2bfloat16(e0), h1 = __float2bfloat16(e1);
            __nv_bfloat16 h2 = __float2bfloat16(e2), h3 = __float2bfloat16(e3);
            __nv_bfloat162 hp0 = __nv_bfloat162(h0, h1);
            __nv_bfloat162 hp1 = __nv_bfloat162(h2, h3);
            __nv_bfloat162 lp0 = __nv_bfloat162(__float2bfloat16(e0 - __bfloat162float(h0)),
                                                __float2bfloat16(e1 - __bfloat162float(h1)));
            __nv_bfloat162 lp1 = __nv_bfloat162(__float2bfloat16(e2 - __bfloat162float(h2)),
                                                __float2bfloat16(e3 - __bfloat162float(h3)));
            *(uint32_t*)(Eh + (size_t)row * SS + col)       = *(uint32_t*)&hp0;
            *(uint32_t*)(Eh + (size_t)(row + 8) * SS + col) = *(uint32_t*)&hp1;
            *(uint32_t*)(El + (size_t)row * SS + col)       = *(uint32_t*)&lp0;
            *(uint32_t*)(El + (size_t)(row + 8) * SS + col) = *(uint32_t*)&lp1;
        }
        // reduce across the 4 lanes sharing this row (lane & 3)
#pragma unroll
        for (int o = 1; o < 4; o <<= 1) {
            rsA += __shfl_xor_sync(0xffffffffu, rsA, o);
            rsB += __shfl_xor_sync(0xffffffffu, rsB, o);
        }
        if ((lane & 3) == 0) {
            atomicAdd(&rsum[row], rsA);
            atomicAdd(&rsum[row + 8], rsB);
        }
    }
}

// ================= PV GEMM via mma.sync bf16, 3-term K-concat, fused normalize ===
// O[:,h*64:+64] = (Eh@Vh + El@Vh + Eh@Vl) / rsum  (K = 3*2048 concat, fp32 accum)
// CTA 128(M) x 64(N), 8 warps (4m x 2n), warp tile 32x32, K-chunk 64.
#define PV_STAGE 24576
#define PV_SMEM  (3 * PV_STAGE)
#define PV_NCHUNK 96

__device__ __forceinline__ void pv_load(
    uint32_t sbase, int slot, int chunk,
    const __nv_bfloat16* __restrict__ Ph, const __nv_bfloat16* __restrict__ Pl,
    const __nv_bfloat16* __restrict__ Vh, const __nv_bfloat16* __restrict__ Vl,
    size_t arow0, size_t brow0, int tid)
{
    const int seg = chunk >> 5;               // 0: Eh*Vh, 1: El*Vh, 2: Eh*Vl
    const int kk  = (chunk & 31) * 64;
    const uint32_t base = sbase + (uint32_t)slot * PV_STAGE;
    {
        const __nv_bfloat16* As = (seg == 1) ? Pl : Ph;
        const int row  = tid >> 1;
        const int half = tid & 1;
        const __nv_bfloat16* arow = As + (arow0 + row) * SS + kk + half * 32;
        const uint32_t roff = (uint32_t)row * 128 + (uint32_t)half * 64;
#pragma unroll
        for (int c = 0; c < 4; c++)
            cpa16(base + sw128(roff + c * 16), arow + c * 8);
    }
    if (tid < 128) {
        const __nv_bfloat16* Bs = (seg == 2) ? Vl : Vh;
        const int row  = tid >> 1;            // 0..63
        const int half = tid & 1;
        const __nv_bfloat16* brow = Bs + (brow0 + row) * SS + kk + half * 32;
        const uint32_t roff = (uint32_t)row * 128 + (uint32_t)half * 64;
#pragma unroll
        for (int c = 0; c < 4; c++)
            cpa16(base + 16384 + sw128(roff + c * 16), brow + c * 8);
    }
}

__global__ __launch_bounds__(256, 2)
void pv_mma_kernel(const __nv_bfloat16* __restrict__ Ph, const __nv_bfloat16* __restrict__ Pl,
                   const __nv_bfloat16* __restrict__ vhTh, const __nv_bfloat16* __restrict__ vhTl,
                   const float* __restrict__ rsum, float* __restrict__ O)
{
    extern __shared__ char smem[];
    const uint32_t sbase = smem_u32(smem);
    const int tid  = threadIdx.x;
    const int wid  = tid >> 5;
    const int lane = tid & 31;
    const int wm   = wid & 3;
    const int wn   = wid >> 2;
    const int bh   = blockIdx.y;
    const int b    = bh >> 3;
    const int h    = bh & 7;
    const int m0   = blockIdx.x * 128;
    const size_t arow0 = (size_t)bh * SS + m0;
    const size_t brow0 = (size_t)b * HID + h * DD;

    float acc[2][4][4];
#pragma unroll
    for (int i = 0; i < 2; i++)
#pragma unroll
        for (int j = 0; j < 4; j++)
#pragma unroll
            for (int r = 0; r < 4; r++) acc[i][j][r] = 0.0f;

#pragma unroll
    for (int j = 0; j < 3; j++) {
        pv_load(sbase, j, j, Ph, Pl, vhTh, vhTl, arow0, brow0, tid);
        asm volatile("cp.async.commit_group;" ::: "memory");
    }

    for (int i = 0; i < PV_NCHUNK; i++) {
        const int s = i % 3;
        asm volatile("cp.async.wait_group 2;" ::: "memory");
        __syncthreads();
        {
            const uint32_t stg = sbase + (uint32_t)s * PV_STAGE;
            const uint32_t aB = stg, bB = stg + 16384;
            const uint32_t a_base = (uint32_t)(wm * 32 + (lane & 15)) * 128 + (uint32_t)((lane >> 4) * 16);
            const uint32_t b_base = (uint32_t)(wn * 32 + (lane & 7) + ((lane >> 4) << 3)) * 128
                                  + (uint32_t)(((lane >> 3) & 1) * 16);
#pragma unroll
            for (int ks = 0; ks < 4; ks++) {
                const uint32_t k0b = (uint32_t)ks * 32;
                uint32_t a[2][4], bfr[4][2];
#pragma unroll
                for (int mb = 0; mb < 2; mb++) {
                    uint32_t sw = sw128(a_base + (uint32_t)mb * 2048 + k0b);
                    ldsm4(a[mb][0], a[mb][1], a[mb][2], a[mb][3], aB + sw);
                }
#pragma unroll
                for (int nb2 = 0; nb2 < 2; nb2++) {
                    uint32_t sw = sw128(b_base + (uint32_t)nb2 * 2048 + k0b);
                    uint32_t r0, r1, r2, r3;
                    ldsm4(r0, r1, r2, r3, bB + sw);
                    bfr[2 * nb2][0] = r0; bfr[2 * nb2][1] = r1;
                    bfr[2 * nb2 + 1][0] = r2; bfr[2 * nb2 + 1][1] = r3;
                }
#pragma unroll
                for (int mb = 0; mb < 2; mb++)
#pragma unroll
                    for (int nb = 0; nb < 4; nb++)
                        mma16816(acc[mb][nb], a[mb], bfr[nb]);
            }
        }
        __syncthreads();
        if (i + 3 < PV_NCHUNK)
            pv_load(sbase, s, i + 3, Ph, Pl, vhTh, vhTl, arow0, brow0, tid);
        asm volatile("cp.async.commit_group;" ::: "memory");
    }

    // epilogue: O[(b*SS + s)*HID + h*64 + col] = acc / rsum[row]
    const int r  = lane >> 2;
    const int c2 = (lane & 3) * 2;
#pragma unroll
    for (int mb = 0; mb < 2; mb++) {
        const int srow = m0 + wm * 32 + mb * 16 + r;
        const float inv0 = 1.0f / rsum[(size_t)bh * SS + srow];
        const float inv1 = 1.0f / rsum[(size_t)bh * SS + srow + 8];
#pragma unroll
        for (int nb = 0; nb < 4; nb++) {
            const int col = wn * 32 + nb * 8 + c2;
            float* o0 = O + ((size_t)b * SS + srow) * HID + h * DD + col;
            *(float2*)o0                     = make_float2(acc[mb][nb][0] * inv0, acc[mb][nb][1] * inv0);
            *(float2*)(o0 + (size_t)8 * HID) = make_float2(acc[mb][nb][2] * inv1, acc[mb][nb][3] * inv1);
        }
    }
}

// ================= w -> bf16 transpose =================
__global__ __launch_bounds__(256)
void convw_kernel(const float* __restrict__ w, __nv_bfloat16* __restrict__ whT)
{
    __shared__ float t[32][33];
    const int b  = blockIdx.z;
    const int k0 = blockIdx.y * 32;
    const int l0 = blockIdx.x * 32;
    const float* wb = w + (size_t)b * SS * SS;
    const int tx = threadIdx.x & 31;
    const int ty = threadIdx.x >> 5;
#pragma unroll
    for (int i = 0; i < 4; i++)
        t[ty + 8 * i][tx] = wb[(size_t)(k0 + ty + 8 * i) * SS + l0 + tx];
    __syncthreads();
#pragma unroll
    for (int i = 0; i < 4; i++) {
        float v = t[tx][ty + 8 * i];
        size_t idx = (size_t)b * SS * SS + (size_t)(l0 + ty + 8 * i) * SS + (k0 + tx);
        whT[idx] = __float2bfloat16(v);
    }
}

// ================= vh -> bf16 hi/lo transpose: [B,S,HID] -> [B,HID,S] =================
__global__ __launch_bounds__(256)
void convv_kernel(const float* __restrict__ vh,
                  __nv_bfloat16* __restrict__ vhTh, __nv_bfloat16* __restrict__ vhTl)
{
    __shared__ float t[32][33];
    const int b  = blockIdx.z;
    const int s0 = blockIdx.y * 32;
    const int d0 = blockIdx.x * 32;
    const int tx = threadIdx.x & 31;
    const int ty = threadIdx.x >> 5;
#pragma unroll
    for (int i = 0; i < 4; i++)
        t[ty + 8 * i][tx] = vh[((size_t)b * SS + s0 + ty + 8 * i) * HID + d0 + tx];
    __syncthreads();
#pragma unroll
    for (int i = 0; i < 4; i++) {
        float v = t[tx][ty + 8 * i];
        size_t idx = ((size_t)b * HID + d0 + ty + 8 * i) * SS + s0 + tx;
        __nv_bfloat16 hv = __float2bfloat16(v);
        vhTh[idx] = hv;
        vhTl[idx] = __float2bfloat16(v - __bfloat162float(hv));
    }
}

// ---------------- fp32 GEMM body (NT + bias), 128x128 tile ----------------
__device__ __forceinline__ void gemm_nt_body(
    const float* __restrict__ A, const float* __restrict__ Bm,
    const float* __restrict__ bias, float* __restrict__ C,
    int N, int K, int lda, int ldb, int ldc, int m0, int n0)
{
    __shared__ float As[16][132];
    __shared__ float Bs[16][132];

    const int tid = threadIdx.x;
    const int tx  = tid & 15;
    const int ty  = tid >> 4;

    float acc[8][8];
#pragma unroll
    for (int i = 0; i < 8; i++)
#pragma unroll
        for (int j = 0; j < 8; j++) acc[i][j] = 0.0f;

    for (int k0 = 0; k0 < K; k0 += 16) {
        const int r  = tid >> 2;
        const int kq = (tid & 3) * 4;
#pragma unroll
        for (int half = 0; half < 2; half++) {
            const int row = r + half * 64;
            float4 v = *(const float4*)(A + (size_t)(m0 + row) * lda + k0 + kq);
            As[kq + 0][row] = v.x; As[kq + 1][row] = v.y;
            As[kq + 2][row] = v.z; As[kq + 3][row] = v.w;
            float4 u = *(const float4*)(Bm + (size_t)(n0 + row) * ldb + k0 + kq);
            Bs[kq + 0][row] = u.x; Bs[kq + 1][row] = u.y;
            Bs[kq + 2][row] = u.z; Bs[kq + 3][row] = u.w;
        }
        __syncthreads();

#pragma unroll
        for (int kk = 0; kk < 16; kk++) {
            float a[8], b[8];
            *(float4*)&a[0] = *(const float4*)&As[kk][ty * 4];
            *(float4*)&a[4] = *(const float4*)&As[kk][64 + ty * 4];
            *(float4*)&b[0] = *(const float4*)&Bs[kk][tx * 4];
            *(float4*)&b[4] = *(const float4*)&Bs[kk][64 + tx * 4];
#pragma unroll
            for (int i = 0; i < 8; i++)
#pragma unroll
                for (int j = 0; j < 8; j++)
                    acc[i][j] = fmaf(a[i], b[j], acc[i][j]);
        }
        __syncthreads();
    }

#pragma unroll
    for (int i = 0; i < 8; i++) {
        const int lm = (i < 4) ? (ty * 4 + i) : (64 + ty * 4 + i - 4);
#pragma unroll
        for (int j = 0; j < 8; j++) {
            const int ln = (j < 4) ? (tx * 4 + j) : (64 + tx * 4 + j - 4);
            C[(size_t)(m0 + lm) * ldc + n0 + ln] = acc[i][j] + bias[n0 + ln];
        }
    }
}

// fused QKV projection
__global__ __launch_bounds__(256)
void qkv_kernel(const float* __restrict__ q, const float* __restrict__ k, const float* __restrict__ v,
                const float* __restrict__ Wq, const float* __restrict__ Wk, const float* __restrict__ Wv,
                const float* __restrict__ bq, const float* __restrict__ bk, const float* __restrict__ bv,
                float* __restrict__ qh, float* __restrict__ kh, float* __restrict__ vh)
{
    const int z = blockIdx.z;
    const float* A  = (z == 0) ? q  : (z == 1) ? k  : v;
    const float* W  = (z == 0) ? Wq : (z == 1) ? Wk : Wv;
    const float* bi = (z == 0) ? bq : (z == 1) ? bk : bv;
    float*       C  = (z == 0) ? qh : (z == 1) ? kh : vh;
    gemm_nt_body(A, W, bi, C, HID, HID, HID, HID, HID,
                 blockIdx.y * 128, blockIdx.x * 128);
}

// output projection
__global__ __launch_bounds__(256)
void outproj_kernel(const float* __restrict__ O, const float* __restrict__ Wo,
                    const float* __restrict__ bo, float* __restrict__ out)
{
    gemm_nt_body(O, Wo, bo, out, HID, HID, HID, HID, HID,
                 blockIdx.y * 128, blockIdx.x * 128);
}

// ---------------- scores: 128x128 tile, K-major smem, 8x8 microtile ----------------
#define SC_SMEM (2 * 64 * 132 * 4)

__global__ __launch_bounds__(256)
void scores_kernel(const float* __restrict__ qhp, const float* __restrict__ khp,
                   const float* __restrict__ attn_bias, const uint4* __restrict__ mask,
                   __nv_bfloat16* __restrict__ Xh)
{
    extern __shared__ char smemraw[];
    float (*qs)[132] = (float (*)[132])smemraw;
    float (*ks)[132] = (float (*)[132])(smemraw + 64 * 132 * 4);

    const int bh = blockIdx.z;
    const int b  = bh >> 3;
    const int h  = bh & 7;
    const int q0 = blockIdx.y * 128;
    const int k0 = blockIdx.x * 128;

    const int tid = threadIdx.x;
    {
        const int m  = tid >> 1;
        const int d0 = (tid & 1) * 32;
        const float* qrow = qhp + (size_t)(b * SS + q0 + m) * HID + h * DD + d0;
        const float* krow = khp + (size_t)(b * SS + k0 + m) * HID + h * DD + d0;
#pragma unroll
        for (int c = 0; c < 8; c++) {
            float4 v = *(const float4*)(qrow + c * 4);
            qs[d0 + c * 4 + 0][m] = v.x; qs[d0 + c * 4 + 1][m] = v.y;
            qs[d0 + c * 4 + 2][m] = v.z; qs[d0 + c * 4 + 3][m] = v.w;
            v = *(const float4*)(krow + c * 4);
            ks[d0 + c * 4 + 0][m] = v.x; ks[d0 + c * 4 + 1][m] = v.y;
            ks[d0 + c * 4 + 2][m] = v.z; ks[d0 + c * 4 + 3][m] = v.w;
        }
    }
    __syncthreads();

    const int tx = tid & 15;
    const int ty = tid >> 4;
    float acc[8][8];
#pragma unroll
    for (int i = 0; i < 8; i++)
#pragma unroll
        for (int j = 0; j < 8; j++) acc[i][j] = 0.0f;

#pragma unroll 4
    for (int d = 0; d < 64; d++) {
        float a[8], bv[8];
        *(float4*)&a[0]  = *(const float4*)&qs[d][ty * 4];
        *(float4*)&a[4]  = *(const float4*)&qs[d][64 + ty * 4];
        *(float4*)&bv[0] = *(const float4*)&ks[d][tx * 4];
        *(float4*)&bv[4] = *(const float4*)&ks[d][64 + tx * 4];
#pragma unroll
        for (int i = 0; i < 8; i++)
#pragma unroll
            for (int j = 0; j < 8; j++)
                acc[i][j] = fmaf(a[i], bv[j], acc[i][j]);
    }

    const float scale = 0.125f;
#pragma unroll
    for (int i = 0; i < 8; i++) {
        const int gq = q0 + ((i < 4) ? (ty * 4 + i) : (64 + ty * 4 + i - 4));
        const size_t mrow = ((size_t)b * SS + gq) * SS;
        const size_t xrow = ((size_t)bh * SS + gq) * SS;
#pragma unroll
        for (int jh = 0; jh < 2; jh++) {
            const int gk = k0 + jh * 64 + tx * 4;
            uint4  mv = mask[(mrow + gk) >> 2];
            float4 bb = *(const float4*)(attn_bias + xrow + gk);
            const float* ac = &acc[i][jh * 4];
            float v0 = mv.x ? 0.0f : fmaf(scale, ac[0], bb.x);
            float v1 = mv.y ? 0.0f : fmaf(scale, ac[1], bb.y);
            float v2 = mv.z ? 0.0f : fmaf(scale, ac[2], bb.z);
            float v3 = mv.w ? 0.0f : fmaf(scale, ac[3], bb.w);
            __nv_bfloat162 hp0 = __nv_bfloat162(__float2bfloat16(v0), __float2bfloat16(v1));
            __nv_bfloat162 hp1 = __nv_bfloat162(__float2bfloat16(v2), __float2bfloat16(v3));
            uint2 hv = make_uint2(*(uint32_t*)&hp0, *(uint32_t*)&hp1);
            *(uint2*)(Xh + xrow + gk) = hv;
        }
    }
}

// ---------------- launch ----------------
extern "C" void kernel_launch(void* const* d_in, const int* in_sizes, int n_in,
                              void* d_out, int out_size)
{
    const float*    q    = (const float*)d_in[0];
    const float*    k    = (const float*)d_in[1];
    const float*    v    = (const float*)d_in[2];
    const float*    bias = (const float*)d_in[3];
    const uint4*    mask = (const uint4*)d_in[4];
    const float*    w    = (const float*)d_in[5];
    const float*    Wq   = (const float*)d_in[6];
    const float*    bq   = (const float*)d_in[7];
    const float*    Wk   = (const float*)d_in[8];
    const float*    bk   = (const float*)d_in[9];
    const float*    Wv   = (const float*)d_in[10];
    const float*    bv   = (const float*)d_in[11];
    const float*    Wo   = (const float*)d_in[12];
    const float*    bo   = (const float*)d_in[13];
    float* out = (float*)d_out;

    float *qh, *kh, *vh, *O, *rsum;
    __nv_bfloat16 *Xh, *whT, *vhTh, *vhTl, *E;
    cudaGetSymbolAddress((void**)&qh,   g_qh);
    cudaGetSymbolAddress((void**)&kh,   g_kh);
    cudaGetSymbolAddress((void**)&vh,   g_vh);
    cudaGetSymbolAddress((void**)&O,    g_O);
    cudaGetSymbolAddress((void**)&Xh,   g_Xh);
    cudaGetSymbolAddress((void**)&whT,  g_whT);
    cudaGetSymbolAddress((void**)&vhTh, g_vhTh);
    cudaGetSymbolAddress((void**)&vhTl, g_vhTl);
    cudaGetSymbolAddress((void**)&E,    g_E);
    cudaGetSymbolAddress((void**)&rsum, g_rsum);

    __nv_bfloat16* Eh = E;
    __nv_bfloat16* El = E + (size_t)BB * NHH * SS * SS;

    cudaFuncSetAttribute(xw_mma_kernel, cudaFuncAttributeMaxDynamicSharedMemorySize, XW_SMEM);
    cudaFuncSetAttribute(pv_mma_kernel, cudaFuncAttributeMaxDynamicSharedMemorySize, PV_SMEM);
    cudaFuncSetAttribute(scores_kernel, cudaFuncAttributeMaxDynamicSharedMemorySize, SC_SMEM);

    // 0) zero row sums; w -> bf16 transposed
    zero_kernel<<<(BB * NHH * SS + 255) / 256, 256>>>(rsum, BB * NHH * SS);
    {
        dim3 grid(SS / 32, SS / 32, BB);
        convw_kernel<<<grid, 256>>>(w, whT);
    }

    // 1) fused QKV projections
    {
        dim3 grid(HID / 128, (BB * SS) / 128, 3);
        qkv_kernel<<<grid, 256>>>(q, k, v, Wq, Wk, Wv, bq, bk, bv, qh, kh, vh);
    }

    // 1b) vh -> bf16 hi/lo transpose
    {
        dim3 grid(HID / 32, SS / 32, BB);
        convv_kernel<<<grid, 256>>>(vh, vhTh, vhTl);
    }

    // 2) scores + bias + mask -> Xh bf16
    {
        dim3 grid(SS / 128, SS / 128, BB * NHH);
        scores_kernel<<<grid, 256, SC_SMEM>>>(qh, kh, bias, mask, Xh);
    }

    // 3) E = exp(Xh @ whT') hi/lo + row sums (fused softmax numerator)
    {
        dim3 grid(SS / 128, (BB * NHH * SS) / 128, 1);
        xw_mma_kernel<<<grid, 256, XW_SMEM>>>(Xh, whT, Eh, El, rsum);
    }

    // 4) O = (E @ vh) / rsum via mma.sync bf16 3-term
    {
        dim3 grid(SS / 128, BB * NHH, 1);
        pv_mma_kernel<<<grid, 256, PV_SMEM>>>(Eh, El, vhTh, vhTl, rsum, O);
    }

    // 5) out = O @ Wo^T + bo
    {
        dim3 grid(HID / 128, (BB * SS) / 128, 1);
        outproj_kernel<<<grid, 256>>>(O, Wo, bo, out);
    }
}

// round 17
// speedup vs baseline: 4.1631x; 1.0055x over previous
#include <cuda_runtime.h>
#include <cuda_bf16.h>
#include <cstdint>
#include <math.h>

// Problem dims
#define BB   2
#define SS   2048
#define HID  512
#define NHH  8
#define DD   64

// ---------------- scratch (static device globals; no allocation) ----------------
__device__ __nv_bfloat16 g_qhb[(size_t)BB * SS * HID];       // bf16 projected q
__device__ __nv_bfloat16 g_khb[(size_t)BB * SS * HID];       // bf16 projected k
__device__ float g_vh[(size_t)BB * SS * HID];
__device__ __nv_bfloat16 g_Xh[(size_t)BB * NHH * SS * SS];   // bf16 masked scores
__device__ __nv_bfloat16 g_whT[(size_t)BB * SS * SS];        // w^T bf16  [b][l][k]
__device__ __nv_bfloat16 g_E[(size_t)2 * BB * NHH * SS * SS];// Eh | El  (exp of logits, hi/lo)
__device__ float g_rsum[(size_t)BB * NHH * SS];              // row sums of exp
__device__ __nv_bfloat16 g_vhTh[(size_t)BB * HID * SS];      // vh^T hi  [b][hd][s]
__device__ __nv_bfloat16 g_vhTl[(size_t)BB * HID * SS];      // vh^T lo
__device__ float g_O [(size_t)BB * SS * HID];

// ================= helpers =================
__device__ __forceinline__ uint32_t smem_u32(const void* p) {
    uint32_t a;
    asm("{ .reg .u64 t; cvta.to.shared.u64 t, %1; cvt.u32.u64 %0, t; }" : "=r"(a) : "l"(p));
    return a;
}
__device__ __forceinline__ uint32_t sw128(uint32_t o) { return o ^ ((o >> 3) & 0x70); }

__device__ __forceinline__ void ldsm4(uint32_t& r0, uint32_t& r1, uint32_t& r2, uint32_t& r3, uint32_t addr) {
    asm volatile("ldmatrix.sync.aligned.m8n8.x4.shared.b16 {%0,%1,%2,%3}, [%4];"
        : "=r"(r0), "=r"(r1), "=r"(r2), "=r"(r3) : "r"(addr));
}
__device__ __forceinline__ void mma16816(float* d, const uint32_t* a, const uint32_t* b) {
    asm volatile("mma.sync.aligned.m16n8k16.row.col.f32.bf16.bf16.f32 "
        "{%0,%1,%2,%3}, {%4,%5,%6,%7}, {%8,%9}, {%0,%1,%2,%3};"
        : "+f"(d[0]), "+f"(d[1]), "+f"(d[2]), "+f"(d[3])
        : "r"(a[0]), "r"(a[1]), "r"(a[2]), "r"(a[3]), "r"(b[0]), "r"(b[1]));
}
__device__ __forceinline__ void cpa16(uint32_t dst, const void* src) {
    asm volatile("cp.async.cg.shared.global [%0], [%1], 16;" :: "r"(dst), "l"(src));
}

// ================= zero rowsum buffer =================
__global__ void zero_kernel(float* __restrict__ p, int n)
{
    int i = blockIdx.x * blockDim.x + threadIdx.x;
    if (i < n) p[i] = 0.0f;
}

// ================= x@w GEMM via mma.sync bf16, fused exp + rowsum =================
// E = exp(Xh @ whT') hi/lo bf16; rsum[row] += sum of exp.  (logits tiny -> no max pass)
// CTA 128x128, 8 warps (4m x 2n), warp tile 32x64, K-chunk 64.
#define XW_STAGE 32768
#define XW_SMEM  (3 * XW_STAGE)
#define XW_NCHUNK 32

__device__ __forceinline__ void xw_load(
    uint32_t sbase, int slot, int chunk,
    const __nv_bfloat16* __restrict__ Xh,
    const __nv_bfloat16* __restrict__ whb,
    int m0, int n0, int tid)
{
    const int kk = chunk * 64;
    const uint32_t base = sbase + (uint32_t)slot * XW_STAGE;
    const int row  = tid >> 1;
    const int half = tid & 1;
    const __nv_bfloat16* arow = Xh  + (size_t)(m0 + row) * SS + kk + half * 32;
    const __nv_bfloat16* brow = whb + (size_t)(n0 + row) * SS + kk + half * 32;
    const uint32_t roff = (uint32_t)row * 128 + (uint32_t)half * 64;
#pragma unroll
    for (int c = 0; c < 4; c++) {
        uint32_t s = sw128(roff + c * 16);
        cpa16(base +         s, arow + c * 8);
        cpa16(base + 16384 + s, brow + c * 8);
    }
}

__device__ __forceinline__ void xw_compute(uint32_t stg, int wm, int wn, int lane,
                                           float acc[2][8][4])
{
    const uint32_t aB = stg, bB = stg + 16384;
    const uint32_t a_base = (uint32_t)(wm * 32 + (lane & 15)) * 128 + (uint32_t)((lane >> 4) * 16);
    const uint32_t b_base = (uint32_t)(wn * 64 + (lane & 7) + ((lane >> 4) << 3)) * 128
                          + (uint32_t)(((lane >> 3) & 1) * 16);
#pragma unroll
    for (int ks = 0; ks < 4; ks++) {
        const uint32_t k0b = (uint32_t)ks * 32;
        uint32_t a[2][4], b[8][2];
#pragma unroll
        for (int mb = 0; mb < 2; mb++) {
            uint32_t s = sw128(a_base + (uint32_t)mb * 2048 + k0b);
            ldsm4(a[mb][0], a[mb][1], a[mb][2], a[mb][3], aB + s);
        }
#pragma unroll
        for (int nb2 = 0; nb2 < 4; nb2++) {
            uint32_t s = sw128(b_base + (uint32_t)nb2 * 2048 + k0b);
            uint32_t r0, r1, r2, r3;
            ldsm4(r0, r1, r2, r3, bB + s);
            b[2 * nb2][0] = r0; b[2 * nb2][1] = r1;
            b[2 * nb2 + 1][0] = r2; b[2 * nb2 + 1][1] = r3;
        }
#pragma unroll
        for (int mb = 0; mb < 2; mb++)
#pragma unroll
            for (int nb = 0; nb < 8; nb++)
                mma16816(acc[mb][nb], a[mb], b[nb]);
    }
}

__global__ __launch_bounds__(256, 2)
void xw_mma_kernel(const __nv_bfloat16* __restrict__ Xh,
                   const __nv_bfloat16* __restrict__ whT,
                   __nv_bfloat16* __restrict__ Eh, __nv_bfloat16* __restrict__ El,
                   float* __restrict__ rsum)
{
    extern __shared__ char smem[];
    const uint32_t sbase = smem_u32(smem);
    const int tid  = threadIdx.x;
    const int wid  = tid >> 5;
    const int lane = tid & 31;
    const int wm   = wid & 3;
    const int wn   = wid >> 2;
    const int n0   = blockIdx.x * 128;
    const int m0   = blockIdx.y * 128;
    const int batch = m0 >> 14;
    const __nv_bfloat16* whb = whT + (size_t)batch * SS * SS;

    float acc[2][8][4];
#pragma unroll
    for (int i = 0; i < 2; i++)
#pragma unroll
        for (int j = 0; j < 8; j++)
#pragma unroll
            for (int r = 0; r < 4; r++) acc[i][j][r] = 0.0f;

#pragma unroll
    for (int j = 0; j < 3; j++) {
        xw_load(sbase, j, j, Xh, whb, m0, n0, tid);
        asm volatile("cp.async.commit_group;" ::: "memory");
    }

    for (int i = 0; i < XW_NCHUNK; i++) {
        const int s = i % 3;
        asm volatile("cp.async.wait_group 2;" ::: "memory");
        __syncthreads();
        xw_compute(sbase + (uint32_t)s * XW_STAGE, wm, wn, lane, acc);
        __syncthreads();
        if (i + 3 < XW_NCHUNK)
            xw_load(sbase, s, i + 3, Xh, whb, m0, n0, tid);
        asm volatile("cp.async.commit_group;" ::: "memory");
    }

    // epilogue: e = exp(acc); write bf16 hi/lo; accumulate row sums
    const int r  = lane >> 2;
    const int c2 = (lane & 3) * 2;
#pragma unroll
    for (int mb = 0; mb < 2; mb++) {
        const int row = m0 + wm * 32 + mb * 16 + r;
        float rsA = 0.0f, rsB = 0.0f;
#pragma unroll
        for (int nb = 0; nb < 8; nb++) {
            const int col = n0 + wn * 64 + nb * 8 + c2;
            float e0 = expf(acc[mb][nb][0]);
            float e1 = expf(acc[mb][nb][1]);
            float e2 = expf(acc[mb][nb][2]);
            float e3 = expf(acc[mb][nb][3]);
            rsA += e0 + e1;
            rsB += e2 + e3;
            __nv_bfloat16 h0 = __float2bfloat16(e0), h1 = __float2bfloat16(e1);
            __nv_bfloat16 h2 = __float2bfloat16(e2), h3 = __float2bfloat16(e3);
            __nv_bfloat162 hp0 = __nv_bfloat162(h0, h1);
            __nv_bfloat162 hp1 = __nv_bfloat162(h2, h3);
            __nv_bfloat162 lp0 = __nv_bfloat162(__float2bfloat16(e0 - __bfloat162float(h0)),
                                                __float2bfloat16(e1 - __bfloat162float(h1)));
            __nv_bfloat162 lp1 = __nv_bfloat162(__float2bfloat16(e2 - __bfloat162float(h2)),
                                                __float2bfloat16(e3 - __bfloat162float(h3)));
            *(uint32_t*)(Eh + (size_t)row * SS + col)       = *(uint32_t*)&hp0;
            *(uint32_t*)(Eh + (size_t)(row + 8) * SS + col) = *(uint32_t*)&hp1;
            *(uint32_t*)(El + (size_t)row * SS + col)       = *(uint32_t*)&lp0;
            *(uint32_t*)(El + (size_t)(row + 8) * SS + col) = *(uint32_t*)&lp1;
        }
#pragma unroll
        for (int o = 1; o < 4; o <<= 1) {
            rsA += __shfl_xor_sync(0xffffffffu, rsA, o);
            rsB += __shfl_xor_sync(0xffffffffu, rsB, o);
        }
        if ((lane & 3) == 0) {
            atomicAdd(&rsum[row], rsA);
            atomicAdd(&rsum[row + 8], rsB);
        }
    }
}

// ================= PV GEMM via mma.sync bf16, 3-term K-concat, fused normalize ===
#define PV_STAGE 24576
#define PV_SMEM  (3 * PV_STAGE)
#define PV_NCHUNK 96

__device__ __forceinline__ void pv_load(
    uint32_t sbase, int slot, int chunk,
    const __nv_bfloat16* __restrict__ Ph, const __nv_bfloat16* __restrict__ Pl,
    const __nv_bfloat16* __restrict__ Vh, const __nv_bfloat16* __restrict__ Vl,
    size_t arow0, size_t brow0, int tid)
{
    const int seg = chunk >> 5;               // 0: Eh*Vh, 1: El*Vh, 2: Eh*Vl
    const int kk  = (chunk & 31) * 64;
    const uint32_t base = sbase + (uint32_t)slot * PV_STAGE;
    {
        const __nv_bfloat16* As = (seg == 1) ? Pl : Ph;
        const int row  = tid >> 1;
        const int half = tid & 1;
        const __nv_bfloat16* arow = As + (arow0 + row) * SS + kk + half * 32;
        const uint32_t roff = (uint32_t)row * 128 + (uint32_t)half * 64;
#pragma unroll
        for (int c = 0; c < 4; c++)
            cpa16(base + sw128(roff + c * 16), arow + c * 8);
    }
    if (tid < 128) {
        const __nv_bfloat16* Bs = (seg == 2) ? Vl : Vh;
        const int row  = tid >> 1;
        const int half = tid & 1;
        const __nv_bfloat16* brow = Bs + (brow0 + row) * SS + kk + half * 32;
        const uint32_t roff = (uint32_t)row * 128 + (uint32_t)half * 64;
#pragma unroll
        for (int c = 0; c < 4; c++)
            cpa16(base + 16384 + sw128(roff + c * 16), brow + c * 8);
    }
}

__global__ __launch_bounds__(256, 2)
void pv_mma_kernel(const __nv_bfloat16* __restrict__ Ph, const __nv_bfloat16* __restrict__ Pl,
                   const __nv_bfloat16* __restrict__ vhTh, const __nv_bfloat16* __restrict__ vhTl,
                   const float* __restrict__ rsum, float* __restrict__ O)
{
    extern __shared__ char smem[];
    const uint32_t sbase = smem_u32(smem);
    const int tid  = threadIdx.x;
    const int wid  = tid >> 5;
    const int lane = tid & 31;
    const int wm   = wid & 3;
    const int wn   = wid >> 2;
    const int bh   = blockIdx.y;
    const int b    = bh >> 3;
    const int h    = bh & 7;
    const int m0   = blockIdx.x * 128;
    const size_t arow0 = (size_t)bh * SS + m0;
    const size_t brow0 = (size_t)b * HID + h * DD;

    float acc[2][4][4];
#pragma unroll
    for (int i = 0; i < 2; i++)
#pragma unroll
        for (int j = 0; j < 4; j++)
#pragma unroll
            for (int r = 0; r < 4; r++) acc[i][j][r] = 0.0f;

#pragma unroll
    for (int j = 0; j < 3; j++) {
        pv_load(sbase, j, j, Ph, Pl, vhTh, vhTl, arow0, brow0, tid);
        asm volatile("cp.async.commit_group;" ::: "memory");
    }

    for (int i = 0; i < PV_NCHUNK; i++) {
        const int s = i % 3;
        asm volatile("cp.async.wait_group 2;" ::: "memory");
        __syncthreads();
        {
            const uint32_t stg = sbase + (uint32_t)s * PV_STAGE;
            const uint32_t aB = stg, bB = stg + 16384;
            const uint32_t a_base = (uint32_t)(wm * 32 + (lane & 15)) * 128 + (uint32_t)((lane >> 4) * 16);
            const uint32_t b_base = (uint32_t)(wn * 32 + (lane & 7) + ((lane >> 4) << 3)) * 128
                                  + (uint32_t)(((lane >> 3) & 1) * 16);
#pragma unroll
            for (int ks = 0; ks < 4; ks++) {
                const uint32_t k0b = (uint32_t)ks * 32;
                uint32_t a[2][4], bfr[4][2];
#pragma unroll
                for (int mb = 0; mb < 2; mb++) {
                    uint32_t sw = sw128(a_base + (uint32_t)mb * 2048 + k0b);
                    ldsm4(a[mb][0], a[mb][1], a[mb][2], a[mb][3], aB + sw);
                }
#pragma unroll
                for (int nb2 = 0; nb2 < 2; nb2++) {
                    uint32_t sw = sw128(b_base + (uint32_t)nb2 * 2048 + k0b);
                    uint32_t r0, r1, r2, r3;
                    ldsm4(r0, r1, r2, r3, bB + sw);
                    bfr[2 * nb2][0] = r0; bfr[2 * nb2][1] = r1;
                    bfr[2 * nb2 + 1][0] = r2; bfr[2 * nb2 + 1][1] = r3;
                }
#pragma unroll
                for (int mb = 0; mb < 2; mb++)
#pragma unroll
                    for (int nb = 0; nb < 4; nb++)
                        mma16816(acc[mb][nb], a[mb], bfr[nb]);
            }
        }
        __syncthreads();
        if (i + 3 < PV_NCHUNK)
            pv_load(sbase, s, i + 3, Ph, Pl, vhTh, vhTl, arow0, brow0, tid);
        asm volatile("cp.async.commit_group;" ::: "memory");
    }

    const int r  = lane >> 2;
    const int c2 = (lane & 3) * 2;
#pragma unroll
    for (int mb = 0; mb < 2; mb++) {
        const int srow = m0 + wm * 32 + mb * 16 + r;
        const float inv0 = 1.0f / rsum[(size_t)bh * SS + srow];
        const float inv1 = 1.0f / rsum[(size_t)bh * SS + srow + 8];
#pragma unroll
        for (int nb = 0; nb < 4; nb++) {
            const int col = wn * 32 + nb * 8 + c2;
            float* o0 = O + ((size_t)b * SS + srow) * HID + h * DD + col;
            *(float2*)o0                     = make_float2(acc[mb][nb][0] * inv0, acc[mb][nb][1] * inv0);
            *(float2*)(o0 + (size_t)8 * HID) = make_float2(acc[mb][nb][2] * inv1, acc[mb][nb][3] * inv1);
        }
    }
}

// ================= scores via mma.sync bf16 =================
// X[b,h,q,k] = mask ? 0 : (0.125 * qh.kh + bias), K=64 single-shot.
// CTA 128x128, 8 warps (4m x 2n). q tile 16KB, k tile 16KB.
#define SCM_SMEM 32768

__global__ __launch_bounds__(256)
void scores_mma_kernel(const __nv_bfloat16* __restrict__ qhb, const __nv_bfloat16* __restrict__ khb,
                       const float* __restrict__ attn_bias, const unsigned* __restrict__ mask,
                       __nv_bfloat16* __restrict__ Xh)
{
    extern __shared__ char smem[];
    const uint32_t sbase = smem_u32(smem);
    const int tid  = threadIdx.x;
    const int wid  = tid >> 5;
    const int lane = tid & 31;
    const int wm   = wid & 3;
    const int wn   = wid >> 2;
    const int bh = blockIdx.x;           // fastest: heads share mask tiles in L2
    const int b  = bh >> 3;
    const int h  = bh & 7;
    const int k0 = blockIdx.y * 128;
    const int q0 = blockIdx.z * 128;

    // load q/k tiles: 128 rows x 64 bf16 (128B rows)
    {
        const int row  = tid >> 1;
        const int half = tid & 1;
        const __nv_bfloat16* qrow = qhb + (size_t)(b * SS + q0 + row) * HID + h * DD + half * 32;
        const __nv_bfloat16* krow = khb + (size_t)(b * SS + k0 + row) * HID + h * DD + half * 32;
        const uint32_t roff = (uint32_t)row * 128 + (uint32_t)half * 64;
#pragma unroll
        for (int c = 0; c < 4; c++) {
            uint32_t s = sw128(roff + c * 16);
            cpa16(sbase +         s, qrow + c * 8);
            cpa16(sbase + 16384 + s, krow + c * 8);
        }
    }
    asm volatile("cp.async.commit_group;" ::: "memory");
    asm volatile("cp.async.wait_group 0;" ::: "memory");
    __syncthreads();

    float acc[2][8][4];
#pragma unroll
    for (int i = 0; i < 2; i++)
#pragma unroll
        for (int j = 0; j < 8; j++)
#pragma unroll
            for (int r = 0; r < 4; r++) acc[i][j][r] = 0.0f;

    xw_compute(sbase, wm, wn, lane, acc);   // same 128B-row layout, K=64 = 4 k16 steps

    // epilogue: scale, +bias, mask, write bf16
    const float scale = 0.125f;
    const int r  = lane >> 2;
    const int c2 = (lane & 3) * 2;
#pragma unroll
    for (int mb = 0; mb < 2; mb++) {
        const int gq = q0 + wm * 32 + mb * 16 + r;
#pragma unroll
        for (int half = 0; half < 2; half++) {
            const int row = gq + half * 8;
            const size_t mrow = ((size_t)b * SS + row) * SS;
            const size_t xrow = ((size_t)bh * SS + row) * SS;
#pragma unroll
            for (int nb = 0; nb < 8; nb++) {
                const int col = k0 + wn * 64 + nb * 8 + c2;
                uint2  mv = *(const uint2*)(mask + mrow + col);
                float2 bb = *(const float2*)(attn_bias + xrow + col);
                float a0 = acc[mb][nb][half * 2 + 0];
                float a1 = acc[mb][nb][half * 2 + 1];
                float v0 = mv.x ? 0.0f : fmaf(scale, a0, bb.x);
                float v1 = mv.y ? 0.0f : fmaf(scale, a1, bb.y);
                __nv_bfloat162 hp = __nv_bfloat162(__float2bfloat16(v0), __float2bfloat16(v1));
                *(uint32_t*)(Xh + xrow + col) = *(uint32_t*)&hp;
            }
        }
    }
}

// ================= w -> bf16 transpose =================
__global__ __launch_bounds__(256)
void convw_kernel(const float* __restrict__ w, __nv_bfloat16* __restrict__ whT)
{
    __shared__ float t[32][33];
    const int b  = blockIdx.z;
    const int k0 = blockIdx.y * 32;
    const int l0 = blockIdx.x * 32;
    const float* wb = w + (size_t)b * SS * SS;
    const int tx = threadIdx.x & 31;
    const int ty = threadIdx.x >> 5;
#pragma unroll
    for (int i = 0; i < 4; i++)
        t[ty + 8 * i][tx] = wb[(size_t)(k0 + ty + 8 * i) * SS + l0 + tx];
    __syncthreads();
#pragma unroll
    for (int i = 0; i < 4; i++) {
        float v = t[tx][ty + 8 * i];
        size_t idx = (size_t)b * SS * SS + (size_t)(l0 + ty + 8 * i) * SS + (k0 + tx);
        whT[idx] = __float2bfloat16(v);
    }
}

// ================= vh -> bf16 hi/lo transpose =================
__global__ __launch_bounds__(256)
void convv_kernel(const float* __restrict__ vh,
                  __nv_bfloat16* __restrict__ vhTh, __nv_bfloat16* __restrict__ vhTl)
{
    __shared__ float t[32][33];
    const int b  = blockIdx.z;
    const int s0 = blockIdx.y * 32;
    const int d0 = blockIdx.x * 32;
    const int tx = threadIdx.x & 31;
    const int ty = threadIdx.x >> 5;
#pragma unroll
    for (int i = 0; i < 4; i++)
        t[ty + 8 * i][tx] = vh[((size_t)b * SS + s0 + ty + 8 * i) * HID + d0 + tx];
    __syncthreads();
#pragma unroll
    for (int i = 0; i < 4; i++) {
        float v = t[tx][ty + 8 * i];
        size_t idx = ((size_t)b * HID + d0 + ty + 8 * i) * SS + s0 + tx;
        __nv_bfloat16 hv = __float2bfloat16(v);
        vhTh[idx] = hv;
        vhTl[idx] = __float2bfloat16(v - __bfloat162float(hv));
    }
}

// ---------------- fp32 GEMM body (NT + bias), 128x128 tile ----------------
template <bool BF16OUT>
__device__ __forceinline__ void gemm_nt_body(
    const float* __restrict__ A, const float* __restrict__ Bm,
    const float* __restrict__ bias, void* __restrict__ Cv,
    int K, int lda, int ldb, int ldc, int m0, int n0)
{
    __shared__ float As[16][132];
    __shared__ float Bs[16][132];

    const int tid = threadIdx.x;
    const int tx  = tid & 15;
    const int ty  = tid >> 4;

    float acc[8][8];
#pragma unroll
    for (int i = 0; i < 8; i++)
#pragma unroll
        for (int j = 0; j < 8; j++) acc[i][j] = 0.0f;

    for (int k0 = 0; k0 < K; k0 += 16) {
        const int r  = tid >> 2;
        const int kq = (tid & 3) * 4;
#pragma unroll
        for (int half = 0; half < 2; half++) {
            const int row = r + half * 64;
            float4 v = *(const float4*)(A + (size_t)(m0 + row) * lda + k0 + kq);
            As[kq + 0][row] = v.x; As[kq + 1][row] = v.y;
            As[kq + 2][row] = v.z; As[kq + 3][row] = v.w;
            float4 u = *(const float4*)(Bm + (size_t)(n0 + row) * ldb + k0 + kq);
            Bs[kq + 0][row] = u.x; Bs[kq + 1][row] = u.y;
            Bs[kq + 2][row] = u.z; Bs[kq + 3][row] = u.w;
        }
        __syncthreads();

#pragma unroll
        for (int kk = 0; kk < 16; kk++) {
            float a[8], b[8];
            *(float4*)&a[0] = *(const float4*)&As[kk][ty * 4];
            *(float4*)&a[4] = *(const float4*)&As[kk][64 + ty * 4];
            *(float4*)&b[0] = *(const float4*)&Bs[kk][tx * 4];
            *(float4*)&b[4] = *(const float4*)&Bs[kk][64 + tx * 4];
#pragma unroll
            for (int i = 0; i < 8; i++)
#pragma unroll
                for (int j = 0; j < 8; j++)
                    acc[i][j] = fmaf(a[i], b[j], acc[i][j]);
        }
        __syncthreads();
    }

#pragma unroll
    for (int i = 0; i < 8; i++) {
        const int lm = (i < 4) ? (ty * 4 + i) : (64 + ty * 4 + i - 4);
#pragma unroll
        for (int j = 0; j < 8; j++) {
            const int ln = (j < 4) ? (tx * 4 + j) : (64 + tx * 4 + j - 4);
            float rres = acc[i][j] + bias[n0 + ln];
            if (BF16OUT)
                ((__nv_bfloat16*)Cv)[(size_t)(m0 + lm) * ldc + n0 + ln] = __float2bfloat16(rres);
            else
                ((float*)Cv)[(size_t)(m0 + lm) * ldc + n0 + ln] = rres;
        }
    }
}

// fused QKV projection: q,k -> bf16; v -> fp32
__global__ __launch_bounds__(256)
void qkv_kernel(const float* __restrict__ q, const float* __restrict__ k, const float* __restrict__ v,
                const float* __restrict__ Wq, const float* __restrict__ Wk, const float* __restrict__ Wv,
                const float* __restrict__ bq, const float* __restrict__ bk, const float* __restrict__ bv,
                __nv_bfloat16* __restrict__ qhb, __nv_bfloat16* __restrict__ khb,
                float* __restrict__ vh)
{
    const int z = blockIdx.z;
    const int m0 = blockIdx.y * 128, n0 = blockIdx.x * 128;
    if (z == 0)
        gemm_nt_body<true >(q, Wq, bq, qhb, HID, HID, HID, HID, m0, n0);
    else if (z == 1)
        gemm_nt_body<true >(k, Wk, bk, khb, HID, HID, HID, HID, m0, n0);
    else
        gemm_nt_body<false>(v, Wv, bv, vh,  HID, HID, HID, HID, m0, n0);
}

// output projection
__global__ __launch_bounds__(256)
void outproj_kernel(const float* __restrict__ O, const float* __restrict__ Wo,
                    const float* __restrict__ bo, float* __restrict__ out)
{
    gemm_nt_body<false>(O, Wo, bo, out, HID, HID, HID, HID,
                        blockIdx.y * 128, blockIdx.x * 128);
}

// ---------------- launch ----------------
extern "C" void kernel_launch(void* const* d_in, const int* in_sizes, int n_in,
                              void* d_out, int out_size)
{
    const float*    q    = (const float*)d_in[0];
    const float*    k    = (const float*)d_in[1];
    const float*    v    = (const float*)d_in[2];
    const float*    bias = (const float*)d_in[3];
    const unsigned* mask = (const unsigned*)d_in[4];
    const float*    w    = (const float*)d_in[5];
    const float*    Wq   = (const float*)d_in[6];
    const float*    bq   = (const float*)d_in[7];
    const float*    Wk   = (const float*)d_in[8];
    const float*    bk   = (const float*)d_in[9];
    const float*    Wv   = (const float*)d_in[10];
    const float*    bv   = (const float*)d_in[11];
    const float*    Wo   = (const float*)d_in[12];
    const float*    bo   = (const float*)d_in[13];
    float* out = (float*)d_out;

    float *vh, *O, *rsum;
    __nv_bfloat16 *qhb, *khb, *Xh, *whT, *vhTh, *vhTl, *E;
    cudaGetSymbolAddress((void**)&qhb,  g_qhb);
    cudaGetSymbolAddress((void**)&khb,  g_khb);
    cudaGetSymbolAddress((void**)&vh,   g_vh);
    cudaGetSymbolAddress((void**)&O,    g_O);
    cudaGetSymbolAddress((void**)&Xh,   g_Xh);
    cudaGetSymbolAddress((void**)&whT,  g_whT);
    cudaGetSymbolAddress((void**)&vhTh, g_vhTh);
    cudaGetSymbolAddress((void**)&vhTl, g_vhTl);
    cudaGetSymbolAddress((void**)&E,    g_E);
    cudaGetSymbolAddress((void**)&rsum, g_rsum);

    __nv_bfloat16* Eh = E;
    __nv_bfloat16* El = E + (size_t)BB * NHH * SS * SS;

    cudaFuncSetAttribute(xw_mma_kernel, cudaFuncAttributeMaxDynamicSharedMemorySize, XW_SMEM);
    cudaFuncSetAttribute(pv_mma_kernel, cudaFuncAttributeMaxDynamicSharedMemorySize, PV_SMEM);
    cudaFuncSetAttribute(scores_mma_kernel, cudaFuncAttributeMaxDynamicSharedMemorySize, SCM_SMEM);

    // 0) zero row sums; w -> bf16 transposed
    zero_kernel<<<(BB * NHH * SS + 255) / 256, 256>>>(rsum, BB * NHH * SS);
    {
        dim3 grid(SS / 32, SS / 32, BB);
        convw_kernel<<<grid, 256>>>(w, whT);
    }

    // 1) fused QKV projections (q,k -> bf16; v -> fp32)
    {
        dim3 grid(HID / 128, (BB * SS) / 128, 3);
        qkv_kernel<<<grid, 256>>>(q, k, v, Wq, Wk, Wv, bq, bk, bv, qhb, khb, vh);
    }

    // 1b) vh -> bf16 hi/lo transpose
    {
        dim3 grid(HID / 32, SS / 32, BB);
        convv_kernel<<<grid, 256>>>(vh, vhTh, vhTl);
    }

    // 2) scores + bias + mask -> Xh bf16 (tensor cores)
    {
        dim3 grid(BB * NHH, SS / 128, SS / 128);
        scores_mma_kernel<<<grid, 256, SCM_SMEM>>>(qhb, khb, bias, mask, Xh);
    }

    // 3) E = exp(Xh @ whT') hi/lo + row sums (fused softmax numerator)
    {
        dim3 grid(SS / 128, (BB * NHH * SS) / 128, 1);
        xw_mma_kernel<<<grid, 256, XW_SMEM>>>(Xh, whT, Eh, El, rsum);
    }

    // 4) O = (E @ vh) / rsum via mma.sync bf16 3-term
    {
        dim3 grid(SS / 128, BB * NHH, 1);
        pv_mma_kernel<<<grid, 256, PV_SMEM>>>(Eh, El, vhTh, vhTl, rsum, O);
    }

    // 5) out = O @ Wo^T + bo
    {
        dim3 grid(HID / 128, (BB * SS) / 128, 1);
        outproj_kernel<<<grid, 256>>>(O, Wo, bo, out);
    }
}